// round 3
// baseline (speedup 1.0000x reference)
#include <cuda_runtime.h>
#include <cuda_bf16.h>
#include <math.h>

// Problem constants
#define B_       2
#define S_       2048
#define DIM_     2048
#define H_       16
#define KV_LORA_ 512
#define NOPE_    128
#define ROPE_    64
#define VD_      128
#define QD_      192          // NOPE_ + ROPE_
#define BS_      (B_ * S_)    // 4096

// ---------------------------------------------------------------------------
// Scratch (static device globals -- no dynamic allocation allowed)
// ---------------------------------------------------------------------------
__device__ float g_q   [BS_ * H_ * QD_];            // 4096 x 3072
__device__ float g_ckv [BS_ * (KV_LORA_ + ROPE_)];  // 4096 x 576
__device__ float g_norm[BS_ * KV_LORA_];            // 4096 x 512
__device__ float g_kv  [BS_ * H_ * (NOPE_ + VD_)];  // 4096 x 4096
__device__ float g_qf  [B_ * H_ * S_ * QD_];        // [B,H,S,192] (pre-scaled)
__device__ float g_kf  [B_ * H_ * S_ * QD_];        // [B,H,S,192]
__device__ float g_v   [B_ * H_ * S_ * VD_];        // [B,H,S,128]
__device__ float g_attn[BS_ * H_ * VD_];            // 4096 x 2048

// ---------------------------------------------------------------------------
// GEMM: C[M,N] = A[M,K] @ B[N,K]^T   (both row-major, fp32)
// 128x128 block tile, BK=8, 256 threads, 8x8 per-thread microtile.
// M, K assumed multiples of 128 / 8 (true for all call sites); N guarded.
// ---------------------------------------------------------------------------
__global__ __launch_bounds__(256) void sgemm_nt(const float* __restrict__ A,
                                                const float* __restrict__ Bm,
                                                float* __restrict__ C,
                                                int M, int N, int K) {
    __shared__ float As[8][136];  // [k][m]
    __shared__ float Bs[8][136];  // [k][n]

    const int t  = threadIdx.x;
    const int ty = t >> 4;        // 0..15
    const int tx = t & 15;        // 0..15
    const int m0 = blockIdx.y * 128;
    const int n0 = blockIdx.x * 128;

    const int lr = t >> 1;        // 0..127 : row within tile
    const int lk = (t & 1) * 4;   // 0 or 4 : k offset

    const float* Aptr = A + (size_t)(m0 + lr) * K + lk;
    const bool   bval = (n0 + lr) < N;
    const float* Bptr = Bm + (size_t)(n0 + lr) * K + lk;

    float acc[8][8];
#pragma unroll
    for (int i = 0; i < 8; i++)
#pragma unroll
        for (int j = 0; j < 8; j++) acc[i][j] = 0.0f;

    for (int k0 = 0; k0 < K; k0 += 8) {
        float4 a4 = *(const float4*)(Aptr + k0);
        float4 b4 = bval ? *(const float4*)(Bptr + k0) : make_float4(0.f, 0.f, 0.f, 0.f);
        As[lk + 0][lr] = a4.x; As[lk + 1][lr] = a4.y;
        As[lk + 2][lr] = a4.z; As[lk + 3][lr] = a4.w;
        Bs[lk + 0][lr] = b4.x; Bs[lk + 1][lr] = b4.y;
        Bs[lk + 2][lr] = b4.z; Bs[lk + 3][lr] = b4.w;
        __syncthreads();

#pragma unroll
        for (int kk = 0; kk < 8; kk++) {
            float4 a0 = *(const float4*)&As[kk][ty * 8];
            float4 a1 = *(const float4*)&As[kk][ty * 8 + 4];
            float4 b0 = *(const float4*)&Bs[kk][tx * 8];
            float4 b1 = *(const float4*)&Bs[kk][tx * 8 + 4];
            float ar[8] = {a0.x, a0.y, a0.z, a0.w, a1.x, a1.y, a1.z, a1.w};
            float br[8] = {b0.x, b0.y, b0.z, b0.w, b1.x, b1.y, b1.z, b1.w};
#pragma unroll
            for (int i = 0; i < 8; i++)
#pragma unroll
                for (int j = 0; j < 8; j++)
                    acc[i][j] = fmaf(ar[i], br[j], acc[i][j]);
        }
        __syncthreads();
    }

#pragma unroll
    for (int i = 0; i < 8; i++) {
        int row = m0 + ty * 8 + i;
#pragma unroll
        for (int j = 0; j < 8; j++) {
            int col = n0 + tx * 8 + j;
            if (col < N) C[(size_t)row * N + col] = acc[i][j];
        }
    }
}

// ---------------------------------------------------------------------------
// RMSNorm over first 512 of each 576-wide row of ckv; scaled by norm_w.
// ---------------------------------------------------------------------------
__global__ __launch_bounds__(128) void rmsnorm_kernel(const float* __restrict__ ckv,
                                                      const float* __restrict__ w,
                                                      float* __restrict__ outp) {
    const int row = blockIdx.x;
    const int t   = threadIdx.x;
    const float* xr = ckv + (size_t)row * (KV_LORA_ + ROPE_);
    float v[4];
    float s = 0.f;
#pragma unroll
    for (int i = 0; i < 4; i++) { v[i] = xr[t + i * 128]; s += v[i] * v[i]; }
#pragma unroll
    for (int m = 16; m >= 1; m >>= 1) s += __shfl_xor_sync(0xffffffffu, s, m);
    __shared__ float ws[4];
    if ((t & 31) == 0) ws[t >> 5] = s;
    __syncthreads();
    s = ws[0] + ws[1] + ws[2] + ws[3];
    const float inv = rsqrtf(s * (1.0f / (float)KV_LORA_) + 1e-6f);
    float* orow = outp + (size_t)row * KV_LORA_;
#pragma unroll
    for (int i = 0; i < 4; i++) orow[t + i * 128] = v[i] * inv * w[t + i * 128];
}

// ---------------------------------------------------------------------------
// RoPE + layout assembly:
//   qf[b,h,s,:]  (192, pre-scaled by 192^-0.5, RoPE on last 64)
//   kf[b,h,s,:]  (192, k_nope | RoPE'd k_rope broadcast over heads)
//   v [b,h,s,:]  (128)
// rope_cache is [S, 128]: cos = cache[s, 0:64], sin = cache[s, 64:128].
// ---------------------------------------------------------------------------
__global__ __launch_bounds__(256) void assemble_kernel(const float* __restrict__ q,
                                                       const float* __restrict__ ckv,
                                                       const float* __restrict__ kv,
                                                       const float* __restrict__ rope,
                                                       float* __restrict__ qf,
                                                       float* __restrict__ kf,
                                                       float* __restrict__ v) {
    const int row = blockIdx.x;       // b*S + s
    const int s   = row & (S_ - 1);
    const int b   = row >> 11;        // S_ == 2048
    const int t   = threadIdx.x;

    __shared__ float cs[64], sn[64], kr[64];
    if (t < 64) {
        cs[t] = rope[(size_t)s * 128 + t];
        sn[t] = rope[(size_t)s * 128 + 64 + t];
    }
    __syncthreads();
    if (t < 64) {
        const float* cr = ckv + (size_t)row * (KV_LORA_ + ROPE_) + KV_LORA_;
        float k0  = cr[t];
        float rot = (t < 32) ? -cr[t + 32] : cr[t - 32];
        kr[t] = k0 * cs[t] + rot * sn[t];
    }
    __syncthreads();

    const float scale = rsqrtf((float)QD_);
    for (int idx = t; idx < H_ * QD_; idx += 256) {
        const int h = idx / QD_;
        const int d = idx - h * QD_;
        const size_t dst = ((size_t)(b * H_ + h) * S_ + s) * QD_ + d;
        const float* qrow = q + (size_t)row * (H_ * QD_) + h * QD_;
        float qv;
        if (d < NOPE_) {
            qv = qrow[d];
        } else {
            const int r   = d - NOPE_;
            float q1  = qrow[NOPE_ + r];
            float rot = (r < 32) ? -qrow[NOPE_ + r + 32] : qrow[NOPE_ + r - 32];
            qv = q1 * cs[r] + rot * sn[r];
        }
        qf[dst] = qv * scale;
        float kvv;
        if (d < NOPE_) kvv = kv[(size_t)row * (H_ * 256) + h * 256 + d];
        else           kvv = kr[d - NOPE_];
        kf[dst] = kvv;
    }
    for (int idx = t; idx < H_ * VD_; idx += 256) {
        const int h  = idx >> 7;
        const int dv = idx & 127;
        v[((size_t)(b * H_ + h) * S_ + s) * VD_ + dv] =
            kv[(size_t)row * (H_ * 256) + h * 256 + NOPE_ + dv];
    }
}

// ---------------------------------------------------------------------------
// Flash-style causal attention, fp32.
// Grid: (S/64, B*H). Block: 256 threads. Per-thread: 4 rows, scores 4 cols
// (interleaved), output 8 cols (interleaved). Online softmax in registers.
// ---------------------------------------------------------------------------
constexpr int FBR = 64, FBC = 64, FD = 192, FDV = 128;
constexpr int QSTR = 196, VSTR = 132, PSTR = 65;
constexpr int FLASH_SMEM_FLOATS = FBR * QSTR + FBC * QSTR + FBC * VSTR + FBR * PSTR;
constexpr unsigned FLASH_SMEM_BYTES = FLASH_SMEM_FLOATS * sizeof(float);

__global__ __launch_bounds__(256) void flash_kernel(const float* __restrict__ Qf,
                                                    const float* __restrict__ Kf,
                                                    const float* __restrict__ Vf,
                                                    float* __restrict__ Out) {
    extern __shared__ float sm[];
    float* Qs = sm;                   // FBR * QSTR
    float* Ks = Qs + FBR * QSTR;      // FBC * QSTR
    float* Vs = Ks + FBC * QSTR;      // FBC * VSTR
    float* Ps = Vs + FBC * VSTR;      // FBR * PSTR

    const int t  = threadIdx.x;
    const int ty = t >> 4, tx = t & 15;
    const int bh = blockIdx.y;
    const int qt = blockIdx.x;
    const int q0 = qt * FBR;
    const int b  = bh >> 4, h = bh & 15;
    const int r0 = ty * 4;

    for (int idx = t; idx < FBR * FD; idx += 256) {
        int r = idx / FD, d = idx - r * FD;
        Qs[r * QSTR + d] = Qf[((size_t)bh * S_ + q0 + r) * FD + d];
    }

    float acc[4][8];
#pragma unroll
    for (int i = 0; i < 4; i++)
#pragma unroll
        for (int j = 0; j < 8; j++) acc[i][j] = 0.0f;
    float mi[4], li[4];
#pragma unroll
    for (int i = 0; i < 4; i++) { mi[i] = -INFINITY; li[i] = 0.0f; }

    for (int j = 0; j <= qt; ++j) {
        __syncthreads();   // prior P@V done before overwriting K/V (and Ps later)
        for (int idx = t; idx < FBC * FD; idx += 256) {
            int r = idx / FD, d = idx - r * FD;
            Ks[r * QSTR + d] = Kf[((size_t)bh * S_ + j * FBC + r) * FD + d];
        }
        for (int idx = t; idx < FBC * FDV; idx += 256) {
            int r = idx >> 7, d = idx & 127;
            Vs[r * VSTR + d] = Vf[((size_t)bh * S_ + j * FBC + r) * FDV + d];
        }
        __syncthreads();

        float sc[4][4];
#pragma unroll
        for (int i = 0; i < 4; i++)
#pragma unroll
            for (int jc = 0; jc < 4; jc++) sc[i][jc] = 0.0f;

#pragma unroll 4
        for (int k = 0; k < FD; ++k) {
            float a0 = Qs[(r0 + 0) * QSTR + k];
            float a1 = Qs[(r0 + 1) * QSTR + k];
            float a2 = Qs[(r0 + 2) * QSTR + k];
            float a3 = Qs[(r0 + 3) * QSTR + k];
            float b0 = Ks[(tx +  0) * QSTR + k];
            float b1 = Ks[(tx + 16) * QSTR + k];
            float b2 = Ks[(tx + 32) * QSTR + k];
            float b3 = Ks[(tx + 48) * QSTR + k];
            sc[0][0] = fmaf(a0, b0, sc[0][0]); sc[0][1] = fmaf(a0, b1, sc[0][1]);
            sc[0][2] = fmaf(a0, b2, sc[0][2]); sc[0][3] = fmaf(a0, b3, sc[0][3]);
            sc[1][0] = fmaf(a1, b0, sc[1][0]); sc[1][1] = fmaf(a1, b1, sc[1][1]);
            sc[1][2] = fmaf(a1, b2, sc[1][2]); sc[1][3] = fmaf(a1, b3, sc[1][3]);
            sc[2][0] = fmaf(a2, b0, sc[2][0]); sc[2][1] = fmaf(a2, b1, sc[2][1]);
            sc[2][2] = fmaf(a2, b2, sc[2][2]); sc[2][3] = fmaf(a2, b3, sc[2][3]);
            sc[3][0] = fmaf(a3, b0, sc[3][0]); sc[3][1] = fmaf(a3, b1, sc[3][1]);
            sc[3][2] = fmaf(a3, b2, sc[3][2]); sc[3][3] = fmaf(a3, b3, sc[3][3]);
        }

        if (j == qt) {
#pragma unroll
            for (int i = 0; i < 4; i++)
#pragma unroll
                for (int jc = 0; jc < 4; jc++)
                    if (j * FBC + tx + jc * 16 > q0 + r0 + i) sc[i][jc] = -1e30f;
        }

#pragma unroll
        for (int i = 0; i < 4; i++) {
            float rm = fmaxf(fmaxf(sc[i][0], sc[i][1]), fmaxf(sc[i][2], sc[i][3]));
#pragma unroll
            for (int msk = 1; msk < 16; msk <<= 1)
                rm = fmaxf(rm, __shfl_xor_sync(0xffffffffu, rm, msk));
            const float mnew = fmaxf(mi[i], rm);
            const float corr = __expf(mi[i] - mnew);
            mi[i] = mnew;
            float rs = 0.f;
#pragma unroll
            for (int jc = 0; jc < 4; jc++) {
                float p = __expf(sc[i][jc] - mnew);
                sc[i][jc] = p;
                rs += p;
            }
#pragma unroll
            for (int msk = 1; msk < 16; msk <<= 1)
                rs += __shfl_xor_sync(0xffffffffu, rs, msk);
            li[i] = li[i] * corr + rs;
#pragma unroll
            for (int jv = 0; jv < 8; jv++) acc[i][jv] *= corr;
#pragma unroll
            for (int jc = 0; jc < 4; jc++)
                Ps[(r0 + i) * PSTR + tx + jc * 16] = sc[i][jc];
        }
        __syncthreads();

#pragma unroll 2
        for (int kk = 0; kk < FBC; ++kk) {
            float p0 = Ps[(r0 + 0) * PSTR + kk];
            float p1 = Ps[(r0 + 1) * PSTR + kk];
            float p2 = Ps[(r0 + 2) * PSTR + kk];
            float p3 = Ps[(r0 + 3) * PSTR + kk];
#pragma unroll
            for (int jv = 0; jv < 8; jv++) {
                float vv = Vs[kk * VSTR + tx + jv * 16];
                acc[0][jv] = fmaf(p0, vv, acc[0][jv]);
                acc[1][jv] = fmaf(p1, vv, acc[1][jv]);
                acc[2][jv] = fmaf(p2, vv, acc[2][jv]);
                acc[3][jv] = fmaf(p3, vv, acc[3][jv]);
            }
        }
    }

#pragma unroll
    for (int i = 0; i < 4; i++) {
        const float linv = 1.0f / li[i];
        const size_t rowo = (size_t)(b * S_ + q0 + r0 + i) * (H_ * VD_) + h * VD_;
#pragma unroll
        for (int jv = 0; jv < 8; jv++)
            Out[rowo + tx + jv * 16] = acc[i][jv] * linv;
    }
}

// ---------------------------------------------------------------------------
// Launch
// ---------------------------------------------------------------------------
extern "C" void kernel_launch(void* const* d_in, const int* in_sizes, int n_in,
                              void* d_out, int out_size) {
    const float* x      = (const float*)d_in[0];
    const float* rope   = (const float*)d_in[1];
    const float* wq     = (const float*)d_in[2];
    const float* wkva   = (const float*)d_in[3];
    const float* norm_w = (const float*)d_in[4];
    const float* wkvb   = (const float*)d_in[5];
    const float* wo     = (const float*)d_in[6];
    float* out = (float*)d_out;

    float *p_q, *p_ckv, *p_norm, *p_kv, *p_qf, *p_kf, *p_v, *p_attn;
    cudaGetSymbolAddress((void**)&p_q,    g_q);
    cudaGetSymbolAddress((void**)&p_ckv,  g_ckv);
    cudaGetSymbolAddress((void**)&p_norm, g_norm);
    cudaGetSymbolAddress((void**)&p_kv,   g_kv);
    cudaGetSymbolAddress((void**)&p_qf,   g_qf);
    cudaGetSymbolAddress((void**)&p_kf,   g_kf);
    cudaGetSymbolAddress((void**)&p_v,    g_v);
    cudaGetSymbolAddress((void**)&p_attn, g_attn);

    cudaFuncSetAttribute(flash_kernel,
                         cudaFuncAttributeMaxDynamicSharedMemorySize,
                         FLASH_SMEM_BYTES);

    // 1) q = x @ wq^T            [4096, 3072]
    {
        dim3 grid((H_ * QD_ + 127) / 128, BS_ / 128);
        sgemm_nt<<<grid, 256>>>(x, wq, p_q, BS_, H_ * QD_, DIM_);
    }
    // 2) ckv = x @ wkva^T        [4096, 576]
    {
        dim3 grid((KV_LORA_ + ROPE_ + 127) / 128, BS_ / 128);
        sgemm_nt<<<grid, 256>>>(x, wkva, p_ckv, BS_, KV_LORA_ + ROPE_, DIM_);
    }
    // 3) RMSNorm(kv_pass)        [4096, 512]
    rmsnorm_kernel<<<BS_, 128>>>(p_ckv, norm_w, p_norm);
    // 4) kv = norm @ wkvb^T      [4096, 4096]
    {
        dim3 grid((H_ * 256 + 127) / 128, BS_ / 128);
        sgemm_nt<<<grid, 256>>>(p_norm, wkvb, p_kv, BS_, H_ * 256, KV_LORA_);
    }
    // 5) RoPE + assemble qf/kf/v in [B,H,S,D] layouts
    assemble_kernel<<<BS_, 256>>>(p_q, p_ckv, p_kv, rope, p_qf, p_kf, p_v);
    // 6) causal flash attention -> attn [4096, 2048]
    {
        dim3 grid(S_ / FBR, B_ * H_);
        flash_kernel<<<grid, 256, FLASH_SMEM_BYTES>>>(p_qf, p_kf, p_v, p_attn);
    }
    // 7) out = attn @ wo^T       [4096, 2048]
    {
        dim3 grid((DIM_ + 127) / 128, BS_ / 128);
        sgemm_nt<<<grid, 256>>>(p_attn, wo, out, BS_, DIM_, DIM_);
    }
}

// round 5
// speedup vs baseline: 1.6876x; 1.6876x over previous
#include <cuda_runtime.h>
#include <cuda_bf16.h>
#include <math.h>
#include <stdint.h>

// Problem constants
#define B_       2
#define S_       2048
#define DIM_     2048
#define H_       16
#define KV_LORA_ 512
#define NOPE_    128
#define ROPE_    64
#define VD_      128
#define QD_      192          // NOPE_ + ROPE_
#define BS_      (B_ * S_)    // 4096

// ---------------------------------------------------------------------------
// Scratch (static device globals -- no dynamic allocation allowed)
// ---------------------------------------------------------------------------
__device__ float g_q   [BS_ * H_ * QD_];            // 4096 x 3072
__device__ float g_ckv [BS_ * (KV_LORA_ + ROPE_)];  // 4096 x 576
__device__ float g_norm[BS_ * KV_LORA_];            // 4096 x 512 (tf32-rounded)
__device__ float g_kv  [BS_ * H_ * (NOPE_ + VD_)];  // 4096 x 4096
__device__ float g_qf  [B_ * H_ * S_ * QD_];
__device__ float g_kf  [B_ * H_ * S_ * QD_];
__device__ float g_v   [B_ * H_ * S_ * VD_];
__device__ float g_attn[BS_ * H_ * VD_];            // tf32-rounded

// tf32-rounded operand copies
__device__ float g_xr   [BS_ * DIM_];                    // 4096 x 2048
__device__ float g_wqr  [H_ * QD_ * DIM_];               // 3072 x 2048
__device__ float g_wkvar[(KV_LORA_ + ROPE_) * DIM_];     // 576  x 2048
__device__ float g_wkvbr[H_ * 256 * KV_LORA_];           // 4096 x 512
__device__ float g_wor  [DIM_ * H_ * VD_];               // 2048 x 2048

// ---------------------------------------------------------------------------
// Helpers
// ---------------------------------------------------------------------------
__device__ __forceinline__ float to_tf32(float x) {
    uint32_t u;
    asm("cvt.rna.tf32.f32 %0, %1;" : "=r"(u) : "f"(x));
    return __uint_as_float(u);
}
__device__ __forceinline__ uint32_t smem_u32(const void* p) {
    uint32_t a;
    asm("{ .reg .u64 t; cvta.to.shared.u64 t, %1; cvt.u32.u64 %0, t; }"
        : "=r"(a) : "l"(p));
    return a;
}
#define CPA16(dst, src, sz) \
    asm volatile("cp.async.cg.shared.global [%0], [%1], 16, %2;" \
                 :: "r"(dst), "l"(src), "r"(sz) : "memory")

// ---------------------------------------------------------------------------
// tf32 mma.sync GEMM: C[M,N] = A[M,K] @ B[N,K]^T (row-major fp32 storage,
// values pre-rounded to tf32). M mult of 128, K mult of 32, N guarded (even).
// CTA 128x128, BK=32, 256 threads = 8 warps, warp tile 64x32 (m16n8k8).
// ---------------------------------------------------------------------------
constexpr int MM_STR  = 36;                 // padded row stride (floats)
constexpr int MM_BUF  = 128 * MM_STR;       // one tile buffer (floats)
constexpr unsigned MM_SMEM_BYTES = 4u * MM_BUF * sizeof(float);  // A0,A1,B0,B1

__global__ __launch_bounds__(256, 2)
void mma_gemm(const float* __restrict__ A, const float* __restrict__ Bm,
              float* __restrict__ C, int N, int K) {
    extern __shared__ float sm[];
    float* As = sm;                 // [2][128][36]
    float* Bs = sm + 2 * MM_BUF;    // [2][128][36]
    const uint32_t As_u = smem_u32(As);
    const uint32_t Bs_u = smem_u32(Bs);

    const int t    = threadIdx.x;
    const int wid  = t >> 5;
    const int lane = t & 31;
    const int g    = lane >> 2;     // groupID 0..7
    const int tig  = lane & 3;      // thread-in-group 0..3
    const int wm   = (wid & 1) * 64;
    const int wn   = (wid >> 1) * 32;
    const int m0   = blockIdx.y * 128;
    const int n0   = blockIdx.x * 128;
    const int NK   = K / 32;

    // cp.async assignments: 4 float4 each for A and B
    int rowi[4], c4i[4], bszi[4];
    const float *Asrc[4], *Bsrc[4];
#pragma unroll
    for (int j = 0; j < 4; j++) {
        const int f = t + j * 256;      // 0..1023
        rowi[j] = f >> 3;
        c4i[j]  = f & 7;
        Asrc[j] = A + (size_t)(m0 + rowi[j]) * K + c4i[j] * 4;
        const int brow = n0 + rowi[j];
        bszi[j] = (brow < N) ? 16 : 0;
        Bsrc[j] = Bm + (size_t)((brow < N) ? brow : 0) * K + c4i[j] * 4;
    }

#define MM_LOAD(buf, kc)                                                        \
    do {                                                                        \
        const int k0_ = (kc) * 32;                                              \
        _Pragma("unroll")                                                       \
        for (int j = 0; j < 4; j++) {                                           \
            const uint32_t off = (uint32_t)((buf) * MM_BUF + rowi[j] * MM_STR + \
                                            c4i[j] * 4) * 4u;                   \
            CPA16(As_u + off, Asrc[j] + k0_, 16);                               \
            CPA16(Bs_u + off, Bsrc[j] + k0_, bszi[j]);                          \
        }                                                                       \
        asm volatile("cp.async.commit_group;" ::: "memory");                    \
    } while (0)

    float acc[4][4][4];
#pragma unroll
    for (int mi = 0; mi < 4; mi++)
#pragma unroll
        for (int ni = 0; ni < 4; ni++)
#pragma unroll
            for (int c = 0; c < 4; c++) acc[mi][ni][c] = 0.0f;

    MM_LOAD(0, 0);
    MM_LOAD(1, 1);

    for (int i = 0; i < NK; ++i) {
        const int cur = i & 1;
        if (i < NK - 1) asm volatile("cp.async.wait_group 1;" ::: "memory");
        else            asm volatile("cp.async.wait_group 0;" ::: "memory");
        __syncthreads();

        const float* Ab = As + cur * MM_BUF;
        const float* Bb = Bs + cur * MM_BUF;
#pragma unroll
        for (int ks = 0; ks < 4; ks++) {
            const int k0 = ks * 8;
            uint32_t a[4][4], b[4][2];
#pragma unroll
            for (int mi = 0; mi < 4; mi++) {
                const float* ap = Ab + (wm + mi * 16 + g) * MM_STR + k0 + tig;
                a[mi][0] = __float_as_uint(ap[0]);
                a[mi][1] = __float_as_uint(ap[8 * MM_STR]);
                a[mi][2] = __float_as_uint(ap[4]);
                a[mi][3] = __float_as_uint(ap[8 * MM_STR + 4]);
            }
#pragma unroll
            for (int ni = 0; ni < 4; ni++) {
                const float* bp = Bb + (wn + ni * 8 + g) * MM_STR + k0 + tig;
                b[ni][0] = __float_as_uint(bp[0]);
                b[ni][1] = __float_as_uint(bp[4]);
            }
#pragma unroll
            for (int mi = 0; mi < 4; mi++)
#pragma unroll
                for (int ni = 0; ni < 4; ni++) {
                    asm volatile(
                        "mma.sync.aligned.m16n8k8.row.col.f32.tf32.tf32.f32 "
                        "{%0,%1,%2,%3}, {%4,%5,%6,%7}, {%8,%9}, {%0,%1,%2,%3};"
                        : "+f"(acc[mi][ni][0]), "+f"(acc[mi][ni][1]),
                          "+f"(acc[mi][ni][2]), "+f"(acc[mi][ni][3])
                        : "r"(a[mi][0]), "r"(a[mi][1]), "r"(a[mi][2]), "r"(a[mi][3]),
                          "r"(b[ni][0]), "r"(b[ni][1]));
                }
        }
        __syncthreads();
        if (i + 2 < NK) MM_LOAD(cur, i + 2);
    }
#undef MM_LOAD

    // Epilogue: direct float2 stores
#pragma unroll
    for (int mi = 0; mi < 4; mi++) {
        const int rr = m0 + wm + mi * 16 + g;
#pragma unroll
        for (int ni = 0; ni < 4; ni++) {
            const int cc = n0 + wn + ni * 8 + tig * 2;
            if (cc < N) {
                float2 v0 = make_float2(acc[mi][ni][0], acc[mi][ni][1]);
                float2 v1 = make_float2(acc[mi][ni][2], acc[mi][ni][3]);
                *(float2*)&C[(size_t)rr * N + cc]       = v0;
                *(float2*)&C[(size_t)(rr + 8) * N + cc] = v1;
            }
        }
    }
}

// ---------------------------------------------------------------------------
// tf32 rounding pass (float4 grid-stride)
// ---------------------------------------------------------------------------
__global__ __launch_bounds__(256) void round_tf32_kernel(const float4* __restrict__ src,
                                                         float4* __restrict__ dst, int n4) {
    for (int i = blockIdx.x * 256 + threadIdx.x; i < n4; i += gridDim.x * 256) {
        float4 v = src[i];
        v.x = to_tf32(v.x); v.y = to_tf32(v.y);
        v.z = to_tf32(v.z); v.w = to_tf32(v.w);
        dst[i] = v;
    }
}

// ---------------------------------------------------------------------------
// RMSNorm over first 512 of each 576-wide row of ckv; output tf32-rounded.
// ---------------------------------------------------------------------------
__global__ __launch_bounds__(128) void rmsnorm_kernel(const float* __restrict__ ckv,
                                                      const float* __restrict__ w,
                                                      float* __restrict__ outp) {
    const int row = blockIdx.x;
    const int t   = threadIdx.x;
    const float* xr = ckv + (size_t)row * (KV_LORA_ + ROPE_);
    float v[4];
    float s = 0.f;
#pragma unroll
    for (int i = 0; i < 4; i++) { v[i] = xr[t + i * 128]; s += v[i] * v[i]; }
#pragma unroll
    for (int m = 16; m >= 1; m >>= 1) s += __shfl_xor_sync(0xffffffffu, s, m);
    __shared__ float ws[4];
    if ((t & 31) == 0) ws[t >> 5] = s;
    __syncthreads();
    s = ws[0] + ws[1] + ws[2] + ws[3];
    const float inv = rsqrtf(s * (1.0f / (float)KV_LORA_) + 1e-6f);
    float* orow = outp + (size_t)row * KV_LORA_;
#pragma unroll
    for (int i = 0; i < 4; i++) orow[t + i * 128] = to_tf32(v[i] * inv * w[t + i * 128]);
}

// ---------------------------------------------------------------------------
// RoPE + layout assembly (rope_cache is [S,128]: cos=0:64, sin=64:128)
// ---------------------------------------------------------------------------
__global__ __launch_bounds__(256) void assemble_kernel(const float* __restrict__ q,
                                                       const float* __restrict__ ckv,
                                                       const float* __restrict__ kv,
                                                       const float* __restrict__ rope,
                                                       float* __restrict__ qf,
                                                       float* __restrict__ kf,
                                                       float* __restrict__ v) {
    const int row = blockIdx.x;       // b*S + s
    const int s   = row & (S_ - 1);
    const int b   = row >> 11;
    const int t   = threadIdx.x;

    __shared__ float cs[64], sn[64], kr[64];
    if (t < 64) {
        cs[t] = rope[(size_t)s * 128 + t];
        sn[t] = rope[(size_t)s * 128 + 64 + t];
    }
    __syncthreads();
    if (t < 64) {
        const float* cr = ckv + (size_t)row * (KV_LORA_ + ROPE_) + KV_LORA_;
        float k0  = cr[t];
        float rot = (t < 32) ? -cr[t + 32] : cr[t - 32];
        kr[t] = k0 * cs[t] + rot * sn[t];
    }
    __syncthreads();

    const float scale = rsqrtf((float)QD_);
    for (int idx = t; idx < H_ * QD_; idx += 256) {
        const int h = idx / QD_;
        const int d = idx - h * QD_;
        const size_t dst = ((size_t)(b * H_ + h) * S_ + s) * QD_ + d;
        const float* qrow = q + (size_t)row * (H_ * QD_) + h * QD_;
        float qv;
        if (d < NOPE_) {
            qv = qrow[d];
        } else {
            const int r   = d - NOPE_;
            float q1  = qrow[NOPE_ + r];
            float rot = (r < 32) ? -qrow[NOPE_ + r + 32] : qrow[NOPE_ + r - 32];
            qv = q1 * cs[r] + rot * sn[r];
        }
        qf[dst] = qv * scale;
        float kvv;
        if (d < NOPE_) kvv = kv[(size_t)row * (H_ * 256) + h * 256 + d];
        else           kvv = kr[d - NOPE_];
        kf[dst] = kvv;
    }
    for (int idx = t; idx < H_ * VD_; idx += 256) {
        const int h  = idx >> 7;
        const int dv = idx & 127;
        v[((size_t)(b * H_ + h) * S_ + s) * VD_ + dv] =
            kv[(size_t)row * (H_ * 256) + h * 256 + NOPE_ + dv];
    }
}

// ---------------------------------------------------------------------------
// Flash-style causal attention, fp32 (output tf32-rounded for wo GEMM).
// ---------------------------------------------------------------------------
constexpr int FBR = 64, FBC = 64, FD = 192, FDV = 128;
constexpr int QSTR = 196, VSTR = 132, PSTR = 65;
constexpr int FLASH_SMEM_FLOATS = FBR * QSTR + FBC * QSTR + FBC * VSTR + FBR * PSTR;
constexpr unsigned FLASH_SMEM_BYTES = FLASH_SMEM_FLOATS * sizeof(float);

__global__ __launch_bounds__(256) void flash_kernel(const float* __restrict__ Qf,
                                                    const float* __restrict__ Kf,
                                                    const float* __restrict__ Vf,
                                                    float* __restrict__ Out) {
    extern __shared__ float fsm[];
    float* Qs = fsm;
    float* Ks = Qs + FBR * QSTR;
    float* Vs = Ks + FBC * QSTR;
    float* Ps = Vs + FBC * VSTR;

    const int t  = threadIdx.x;
    const int ty = t >> 4, tx = t & 15;
    const int bh = blockIdx.y;
    const int qt = blockIdx.x;
    const int q0 = qt * FBR;
    const int b  = bh >> 4, h = bh & 15;
    const int r0 = ty * 4;

    for (int idx = t; idx < FBR * FD; idx += 256) {
        int r = idx / FD, d = idx - r * FD;
        Qs[r * QSTR + d] = Qf[((size_t)bh * S_ + q0 + r) * FD + d];
    }

    float acc[4][8];
#pragma unroll
    for (int i = 0; i < 4; i++)
#pragma unroll
        for (int j = 0; j < 8; j++) acc[i][j] = 0.0f;
    float mi[4], li[4];
#pragma unroll
    for (int i = 0; i < 4; i++) { mi[i] = -INFINITY; li[i] = 0.0f; }

    for (int j = 0; j <= qt; ++j) {
        __syncthreads();
        for (int idx = t; idx < FBC * FD; idx += 256) {
            int r = idx / FD, d = idx - r * FD;
            Ks[r * QSTR + d] = Kf[((size_t)bh * S_ + j * FBC + r) * FD + d];
        }
        for (int idx = t; idx < FBC * FDV; idx += 256) {
            int r = idx >> 7, d = idx & 127;
            Vs[r * VSTR + d] = Vf[((size_t)bh * S_ + j * FBC + r) * FDV + d];
        }
        __syncthreads();

        float sc[4][4];
#pragma unroll
        for (int i = 0; i < 4; i++)
#pragma unroll
            for (int jc = 0; jc < 4; jc++) sc[i][jc] = 0.0f;

#pragma unroll 4
        for (int k = 0; k < FD; ++k) {
            float a0 = Qs[(r0 + 0) * QSTR + k];
            float a1 = Qs[(r0 + 1) * QSTR + k];
            float a2 = Qs[(r0 + 2) * QSTR + k];
            float a3 = Qs[(r0 + 3) * QSTR + k];
            float b0 = Ks[(tx +  0) * QSTR + k];
            float b1 = Ks[(tx + 16) * QSTR + k];
            float b2 = Ks[(tx + 32) * QSTR + k];
            float b3 = Ks[(tx + 48) * QSTR + k];
            sc[0][0] = fmaf(a0, b0, sc[0][0]); sc[0][1] = fmaf(a0, b1, sc[0][1]);
            sc[0][2] = fmaf(a0, b2, sc[0][2]); sc[0][3] = fmaf(a0, b3, sc[0][3]);
            sc[1][0] = fmaf(a1, b0, sc[1][0]); sc[1][1] = fmaf(a1, b1, sc[1][1]);
            sc[1][2] = fmaf(a1, b2, sc[1][2]); sc[1][3] = fmaf(a1, b3, sc[1][3]);
            sc[2][0] = fmaf(a2, b0, sc[2][0]); sc[2][1] = fmaf(a2, b1, sc[2][1]);
            sc[2][2] = fmaf(a2, b2, sc[2][2]); sc[2][3] = fmaf(a2, b3, sc[2][3]);
            sc[3][0] = fmaf(a3, b0, sc[3][0]); sc[3][1] = fmaf(a3, b1, sc[3][1]);
            sc[3][2] = fmaf(a3, b2, sc[3][2]); sc[3][3] = fmaf(a3, b3, sc[3][3]);
        }

        if (j == qt) {
#pragma unroll
            for (int i = 0; i < 4; i++)
#pragma unroll
                for (int jc = 0; jc < 4; jc++)
                    if (j * FBC + tx + jc * 16 > q0 + r0 + i) sc[i][jc] = -1e30f;
        }

#pragma unroll
        for (int i = 0; i < 4; i++) {
            float rm = fmaxf(fmaxf(sc[i][0], sc[i][1]), fmaxf(sc[i][2], sc[i][3]));
#pragma unroll
            for (int msk = 1; msk < 16; msk <<= 1)
                rm = fmaxf(rm, __shfl_xor_sync(0xffffffffu, rm, msk));
            const float mnew = fmaxf(mi[i], rm);
            const float corr = __expf(mi[i] - mnew);
            mi[i] = mnew;
            float rs = 0.f;
#pragma unroll
            for (int jc = 0; jc < 4; jc++) {
                float p = __expf(sc[i][jc] - mnew);
                sc[i][jc] = p;
                rs += p;
            }
#pragma unroll
            for (int msk = 1; msk < 16; msk <<= 1)
                rs += __shfl_xor_sync(0xffffffffu, rs, msk);
            li[i] = li[i] * corr + rs;
#pragma unroll
            for (int jv = 0; jv < 8; jv++) acc[i][jv] *= corr;
#pragma unroll
            for (int jc = 0; jc < 4; jc++)
                Ps[(r0 + i) * PSTR + tx + jc * 16] = sc[i][jc];
        }
        __syncthreads();

#pragma unroll 2
        for (int kk = 0; kk < FBC; ++kk) {
            float p0 = Ps[(r0 + 0) * PSTR + kk];
            float p1 = Ps[(r0 + 1) * PSTR + kk];
            float p2 = Ps[(r0 + 2) * PSTR + kk];
            float p3 = Ps[(r0 + 3) * PSTR + kk];
#pragma unroll
            for (int jv = 0; jv < 8; jv++) {
                float vv = Vs[kk * VSTR + tx + jv * 16];
                acc[0][jv] = fmaf(p0, vv, acc[0][jv]);
                acc[1][jv] = fmaf(p1, vv, acc[1][jv]);
                acc[2][jv] = fmaf(p2, vv, acc[2][jv]);
                acc[3][jv] = fmaf(p3, vv, acc[3][jv]);
            }
        }
    }

#pragma unroll
    for (int i = 0; i < 4; i++) {
        const float linv = 1.0f / li[i];
        const size_t rowo = (size_t)(b * S_ + q0 + r0 + i) * (H_ * VD_) + h * VD_;
#pragma unroll
        for (int jv = 0; jv < 8; jv++)
            Out[rowo + tx + jv * 16] = to_tf32(acc[i][jv] * linv);
    }
}

// ---------------------------------------------------------------------------
// Launch
// ---------------------------------------------------------------------------
extern "C" void kernel_launch(void* const* d_in, const int* in_sizes, int n_in,
                              void* d_out, int out_size) {
    const float* x      = (const float*)d_in[0];
    const float* rope   = (const float*)d_in[1];
    const float* wq     = (const float*)d_in[2];
    const float* wkva   = (const float*)d_in[3];
    const float* norm_w = (const float*)d_in[4];
    const float* wkvb   = (const float*)d_in[5];
    const float* wo     = (const float*)d_in[6];
    float* out = (float*)d_out;

    float *p_q, *p_ckv, *p_norm, *p_kv, *p_qf, *p_kf, *p_v, *p_attn;
    float *p_xr, *p_wqr, *p_wkvar, *p_wkvbr, *p_wor;
    cudaGetSymbolAddress((void**)&p_q,     g_q);
    cudaGetSymbolAddress((void**)&p_ckv,   g_ckv);
    cudaGetSymbolAddress((void**)&p_norm,  g_norm);
    cudaGetSymbolAddress((void**)&p_kv,    g_kv);
    cudaGetSymbolAddress((void**)&p_qf,    g_qf);
    cudaGetSymbolAddress((void**)&p_kf,    g_kf);
    cudaGetSymbolAddress((void**)&p_v,     g_v);
    cudaGetSymbolAddress((void**)&p_attn,  g_attn);
    cudaGetSymbolAddress((void**)&p_xr,    g_xr);
    cudaGetSymbolAddress((void**)&p_wqr,   g_wqr);
    cudaGetSymbolAddress((void**)&p_wkvar, g_wkvar);
    cudaGetSymbolAddress((void**)&p_wkvbr, g_wkvbr);
    cudaGetSymbolAddress((void**)&p_wor,   g_wor);

    cudaFuncSetAttribute(flash_kernel, cudaFuncAttributeMaxDynamicSharedMemorySize,
                         FLASH_SMEM_BYTES);
    cudaFuncSetAttribute(mma_gemm, cudaFuncAttributeMaxDynamicSharedMemorySize,
                         MM_SMEM_BYTES);

    // 0) round operands to tf32 (GEMM HW then truncates losslessly)
    {
        int n;
        n = BS_ * DIM_ / 4;
        round_tf32_kernel<<<1024, 256>>>((const float4*)x, (float4*)p_xr, n);
        n = H_ * QD_ * DIM_ / 4;
        round_tf32_kernel<<<1024, 256>>>((const float4*)wq, (float4*)p_wqr, n);
        n = (KV_LORA_ + ROPE_) * DIM_ / 4;
        round_tf32_kernel<<<512, 256>>>((const float4*)wkva, (float4*)p_wkvar, n);
        n = H_ * 256 * KV_LORA_ / 4;
        round_tf32_kernel<<<512, 256>>>((const float4*)wkvb, (float4*)p_wkvbr, n);
        n = DIM_ * H_ * VD_ / 4;
        round_tf32_kernel<<<1024, 256>>>((const float4*)wo, (float4*)p_wor, n);
    }

    // 1) q = x @ wq^T            [4096, 3072]
    mma_gemm<<<dim3(24, 32), 256, MM_SMEM_BYTES>>>(p_xr, p_wqr, p_q, H_ * QD_, DIM_);
    // 2) ckv = x @ wkva^T        [4096, 576]
    mma_gemm<<<dim3(5, 32), 256, MM_SMEM_BYTES>>>(p_xr, p_wkvar, p_ckv, KV_LORA_ + ROPE_, DIM_);
    // 3) RMSNorm
    rmsnorm_kernel<<<BS_, 128>>>(p_ckv, norm_w, p_norm);
    // 4) kv = norm @ wkvb^T      [4096, 4096]
    mma_gemm<<<dim3(32, 32), 256, MM_SMEM_BYTES>>>(p_norm, p_wkvbr, p_kv, H_ * 256, KV_LORA_);
    // 5) RoPE + assemble
    assemble_kernel<<<BS_, 256>>>(p_q, p_ckv, p_kv, rope, p_qf, p_kf, p_v);
    // 6) causal flash attention
    flash_kernel<<<dim3(S_ / FBR, B_ * H_), 256, FLASH_SMEM_BYTES>>>(p_qf, p_kf, p_v, p_attn);
    // 7) out = attn @ wo^T       [4096, 2048]
    mma_gemm<<<dim3(16, 32), 256, MM_SMEM_BYTES>>>(p_attn, p_wor, out, DIM_, DIM_);
}

// round 9
// speedup vs baseline: 4.6609x; 2.7619x over previous
#include <cuda_runtime.h>
#include <cuda_bf16.h>
#include <math.h>
#include <stdint.h>

// Problem constants
#define B_       2
#define S_       2048
#define DIM_     2048
#define H_       16
#define KV_LORA_ 512
#define NOPE_    128
#define ROPE_    64
#define VD_      128
#define QD_      192
#define BS_      (B_ * S_)    // 4096

// ---------------------------------------------------------------------------
// Scratch
// ---------------------------------------------------------------------------
__device__ float g_q   [BS_ * H_ * QD_];
__device__ float g_ckv [BS_ * (KV_LORA_ + ROPE_)];
__device__ float g_norm[BS_ * KV_LORA_];
__device__ float g_kv  [BS_ * H_ * (NOPE_ + VD_)];
__device__ float g_qf  [B_ * H_ * S_ * QD_];   // tf32-rounded, pre-scaled
__device__ float g_kf  [B_ * H_ * S_ * QD_];   // tf32-rounded
__device__ float g_v   [B_ * H_ * S_ * VD_];   // tf32-rounded
__device__ float g_attn[BS_ * H_ * VD_];       // tf32-rounded

__device__ float g_xr   [BS_ * DIM_];
__device__ float g_wqr  [H_ * QD_ * DIM_];
__device__ float g_wkvar[(KV_LORA_ + ROPE_) * DIM_];
__device__ float g_wkvbr[H_ * 256 * KV_LORA_];
__device__ float g_wor  [DIM_ * H_ * VD_];

// ---------------------------------------------------------------------------
// Helpers
// ---------------------------------------------------------------------------
__device__ __forceinline__ float to_tf32(float x) {
    uint32_t u;
    asm("cvt.rna.tf32.f32 %0, %1;" : "=r"(u) : "f"(x));
    return __uint_as_float(u);
}
__device__ __forceinline__ uint32_t smem_u32(const void* p) {
    uint32_t a;
    asm("{ .reg .u64 t; cvta.to.shared.u64 t, %1; cvt.u32.u64 %0, t; }"
        : "=r"(a) : "l"(p));
    return a;
}
#define CPA16(dst, src, sz) \
    asm volatile("cp.async.cg.shared.global [%0], [%1], 16, %2;" \
                 :: "r"(dst), "l"(src), "r"(sz) : "memory")
#define MMA_TF32(d, a, b)                                                     \
    asm volatile(                                                             \
        "mma.sync.aligned.m16n8k8.row.col.f32.tf32.tf32.f32 "                 \
        "{%0,%1,%2,%3}, {%4,%5,%6,%7}, {%8,%9}, {%0,%1,%2,%3};"               \
        : "+f"((d)[0]), "+f"((d)[1]), "+f"((d)[2]), "+f"((d)[3])              \
        : "r"((a)[0]), "r"((a)[1]), "r"((a)[2]), "r"((a)[3]),                 \
          "r"((b)[0]), "r"((b)[1]))

// ---------------------------------------------------------------------------
// tf32 mma.sync GEMM (unchanged from R5, passing)
// ---------------------------------------------------------------------------
constexpr int MM_STR  = 36;
constexpr int MM_BUF  = 128 * MM_STR;
constexpr unsigned MM_SMEM_BYTES = 4u * MM_BUF * sizeof(float);

__global__ __launch_bounds__(256, 2)
void mma_gemm(const float* __restrict__ A, const float* __restrict__ Bm,
              float* __restrict__ C, int N, int K) {
    extern __shared__ float sm[];
    float* As = sm;
    float* Bs = sm + 2 * MM_BUF;
    const uint32_t As_u = smem_u32(As);
    const uint32_t Bs_u = smem_u32(Bs);

    const int t    = threadIdx.x;
    const int wid  = t >> 5;
    const int lane = t & 31;
    const int g    = lane >> 2;
    const int tig  = lane & 3;
    const int wm   = (wid & 1) * 64;
    const int wn   = (wid >> 1) * 32;
    const int m0   = blockIdx.y * 128;
    const int n0   = blockIdx.x * 128;
    const int NK   = K / 32;

    int rowi[4], c4i[4], bszi[4];
    const float *Asrc[4], *Bsrc[4];
#pragma unroll
    for (int j = 0; j < 4; j++) {
        const int f = t + j * 256;
        rowi[j] = f >> 3;
        c4i[j]  = f & 7;
        Asrc[j] = A + (size_t)(m0 + rowi[j]) * K + c4i[j] * 4;
        const int brow = n0 + rowi[j];
        bszi[j] = (brow < N) ? 16 : 0;
        Bsrc[j] = Bm + (size_t)((brow < N) ? brow : 0) * K + c4i[j] * 4;
    }

#define MM_LOAD(buf, kc)                                                        \
    do {                                                                        \
        const int k0_ = (kc) * 32;                                              \
        _Pragma("unroll")                                                       \
        for (int j = 0; j < 4; j++) {                                           \
            const uint32_t off = (uint32_t)((buf) * MM_BUF + rowi[j] * MM_STR + \
                                            c4i[j] * 4) * 4u;                   \
            CPA16(As_u + off, Asrc[j] + k0_, 16);                               \
            CPA16(Bs_u + off, Bsrc[j] + k0_, bszi[j]);                          \
        }                                                                       \
        asm volatile("cp.async.commit_group;" ::: "memory");                    \
    } while (0)

    float acc[4][4][4];
#pragma unroll
    for (int mi = 0; mi < 4; mi++)
#pragma unroll
        for (int ni = 0; ni < 4; ni++)
#pragma unroll
            for (int c = 0; c < 4; c++) acc[mi][ni][c] = 0.0f;

    MM_LOAD(0, 0);
    MM_LOAD(1, 1);

    for (int i = 0; i < NK; ++i) {
        const int cur = i & 1;
        if (i < NK - 1) asm volatile("cp.async.wait_group 1;" ::: "memory");
        else            asm volatile("cp.async.wait_group 0;" ::: "memory");
        __syncthreads();

        const float* Ab = As + cur * MM_BUF;
        const float* Bb = Bs + cur * MM_BUF;
#pragma unroll
        for (int ks = 0; ks < 4; ks++) {
            const int k0 = ks * 8;
            uint32_t a[4][4], b[4][2];
#pragma unroll
            for (int mi = 0; mi < 4; mi++) {
                const float* ap = Ab + (wm + mi * 16 + g) * MM_STR + k0 + tig;
                a[mi][0] = __float_as_uint(ap[0]);
                a[mi][1] = __float_as_uint(ap[8 * MM_STR]);
                a[mi][2] = __float_as_uint(ap[4]);
                a[mi][3] = __float_as_uint(ap[8 * MM_STR + 4]);
            }
#pragma unroll
            for (int ni = 0; ni < 4; ni++) {
                const float* bp = Bb + (wn + ni * 8 + g) * MM_STR + k0 + tig;
                b[ni][0] = __float_as_uint(bp[0]);
                b[ni][1] = __float_as_uint(bp[4]);
            }
#pragma unroll
            for (int mi = 0; mi < 4; mi++)
#pragma unroll
                for (int ni = 0; ni < 4; ni++)
                    MMA_TF32(acc[mi][ni], a[mi], b[ni]);
        }
        __syncthreads();
        if (i + 2 < NK) MM_LOAD(cur, i + 2);
    }
#undef MM_LOAD

#pragma unroll
    for (int mi = 0; mi < 4; mi++) {
        const int rr = m0 + wm + mi * 16 + g;
#pragma unroll
        for (int ni = 0; ni < 4; ni++) {
            const int cc = n0 + wn + ni * 8 + tig * 2;
            if (cc < N) {
                float2 v0 = make_float2(acc[mi][ni][0], acc[mi][ni][1]);
                float2 v1 = make_float2(acc[mi][ni][2], acc[mi][ni][3]);
                *(float2*)&C[(size_t)rr * N + cc]       = v0;
                *(float2*)&C[(size_t)(rr + 8) * N + cc] = v1;
            }
        }
    }
}

// ---------------------------------------------------------------------------
// tf32 rounding pass
// ---------------------------------------------------------------------------
__global__ __launch_bounds__(256) void round_tf32_kernel(const float4* __restrict__ src,
                                                         float4* __restrict__ dst, int n4) {
    for (int i = blockIdx.x * 256 + threadIdx.x; i < n4; i += gridDim.x * 256) {
        float4 v = src[i];
        v.x = to_tf32(v.x); v.y = to_tf32(v.y);
        v.z = to_tf32(v.z); v.w = to_tf32(v.w);
        dst[i] = v;
    }
}

// ---------------------------------------------------------------------------
// RMSNorm (tf32-rounded out)
// ---------------------------------------------------------------------------
__global__ __launch_bounds__(128) void rmsnorm_kernel(const float* __restrict__ ckv,
                                                      const float* __restrict__ w,
                                                      float* __restrict__ outp) {
    const int row = blockIdx.x;
    const int t   = threadIdx.x;
    const float* xr = ckv + (size_t)row * (KV_LORA_ + ROPE_);
    float v[4];
    float s = 0.f;
#pragma unroll
    for (int i = 0; i < 4; i++) { v[i] = xr[t + i * 128]; s += v[i] * v[i]; }
#pragma unroll
    for (int m = 16; m >= 1; m >>= 1) s += __shfl_xor_sync(0xffffffffu, s, m);
    __shared__ float ws[4];
    if ((t & 31) == 0) ws[t >> 5] = s;
    __syncthreads();
    s = ws[0] + ws[1] + ws[2] + ws[3];
    const float inv = rsqrtf(s * (1.0f / (float)KV_LORA_) + 1e-6f);
    float* orow = outp + (size_t)row * KV_LORA_;
#pragma unroll
    for (int i = 0; i < 4; i++) orow[t + i * 128] = to_tf32(v[i] * inv * w[t + i * 128]);
}

// ---------------------------------------------------------------------------
// RoPE + assembly; outputs tf32-rounded (rope cache [S,128]: cos|sin)
// ---------------------------------------------------------------------------
__global__ __launch_bounds__(256) void assemble_kernel(const float* __restrict__ q,
                                                       const float* __restrict__ ckv,
                                                       const float* __restrict__ kv,
                                                       const float* __restrict__ rope,
                                                       float* __restrict__ qf,
                                                       float* __restrict__ kf,
                                                       float* __restrict__ v) {
    const int row = blockIdx.x;
    const int s   = row & (S_ - 1);
    const int b   = row >> 11;
    const int t   = threadIdx.x;

    __shared__ float cs[64], sn[64], kr[64];
    if (t < 64) {
        cs[t] = rope[(size_t)s * 128 + t];
        sn[t] = rope[(size_t)s * 128 + 64 + t];
    }
    __syncthreads();
    if (t < 64) {
        const float* cr = ckv + (size_t)row * (KV_LORA_ + ROPE_) + KV_LORA_;
        float k0  = cr[t];
        float rot = (t < 32) ? -cr[t + 32] : cr[t - 32];
        kr[t] = k0 * cs[t] + rot * sn[t];
    }
    __syncthreads();

    const float scale = rsqrtf((float)QD_);
    for (int idx = t; idx < H_ * QD_; idx += 256) {
        const int h = idx / QD_;
        const int d = idx - h * QD_;
        const size_t dst = ((size_t)(b * H_ + h) * S_ + s) * QD_ + d;
        const float* qrow = q + (size_t)row * (H_ * QD_) + h * QD_;
        float qv;
        if (d < NOPE_) {
            qv = qrow[d];
        } else {
            const int r   = d - NOPE_;
            float q1  = qrow[NOPE_ + r];
            float rot = (r < 32) ? -qrow[NOPE_ + r + 32] : qrow[NOPE_ + r - 32];
            qv = q1 * cs[r] + rot * sn[r];
        }
        qf[dst] = to_tf32(qv * scale);
        float kvv;
        if (d < NOPE_) kvv = kv[(size_t)row * (H_ * 256) + h * 256 + d];
        else           kvv = kr[d - NOPE_];
        kf[dst] = to_tf32(kvv);
    }
    for (int idx = t; idx < H_ * VD_; idx += 256) {
        const int h  = idx >> 7;
        const int dv = idx & 127;
        v[((size_t)(b * H_ + h) * S_ + s) * VD_ + dv] =
            to_tf32(kv[(size_t)row * (H_ * 256) + h * 256 + NOPE_ + dv]);
    }
}

// ---------------------------------------------------------------------------
// Tensor-core causal flash attention (tf32 mma.sync).
// BR=BC=64, 256 threads = 8 warps (4 row x 2 col). Q frags in registers.
// K/V double-buffered cp.async. Grid: (B*H, 32 qtiles reversed).
// SMEM floats: K0 | V0 | K1 | V1 | Ps | redM | redS
// ---------------------------------------------------------------------------
constexpr int FK0 = 0;
constexpr int FV0 = 12544;              // 64*196
constexpr int FK1 = 21248;              // FV0 + 64*136
constexpr int FV1 = 33792;
constexpr int FPS = 42496;              // stride 68
constexpr int FRM = 46848;              // 128
constexpr int FRS = 46976;              // 128
constexpr unsigned FL_SMEM_BYTES = 47104u * 4u;   // 184 KB

__global__ __launch_bounds__(256, 1)
void flash_mma(const float* __restrict__ Qf, const float* __restrict__ Kf,
               const float* __restrict__ Vf, float* __restrict__ Out) {
    extern __shared__ float sm[];
    const uint32_t sb = smem_u32(sm);

    const int t    = threadIdx.x;
    const int wid  = t >> 5;
    const int lane = t & 31;
    const int g    = lane >> 2;
    const int tig  = lane & 3;
    const int wr   = wid >> 1;           // 0..3  (16-row group)
    const int wc   = wid & 1;            // 0..1  (32-col half / 64-col O half)
    const int bh   = blockIdx.x;
    const int qt   = (int)gridDim.y - 1 - (int)blockIdx.y;  // big tiles first
    const int q0   = qt * 64;
    const int b    = bh >> 4, h = bh & 15;

    const float* Kbase = Kf + (size_t)bh * S_ * QD_;
    const float* Vbase = Vf + (size_t)bh * S_ * VD_;

#define KV_LOAD(bufK, bufV, jj)                                                 \
    do {                                                                        \
        const float* Kb_ = Kbase + (size_t)(jj) * 64 * QD_;                     \
        const float* Vb_ = Vbase + (size_t)(jj) * 64 * VD_;                     \
        _Pragma("unroll")                                                       \
        for (int i_ = 0; i_ < 12; i_++) {                                       \
            const int f_ = t + i_ * 256;                                        \
            const int r_ = f_ / 48, c_ = (f_ % 48) * 4;                         \
            CPA16(sb + (uint32_t)((bufK) + r_ * 196 + c_) * 4u,                 \
                  Kb_ + r_ * QD_ + c_, 16);                                     \
        }                                                                       \
        _Pragma("unroll")                                                       \
        for (int i_ = 0; i_ < 8; i_++) {                                        \
            const int f_ = t + i_ * 256;                                        \
            const int r_ = f_ >> 5, c_ = (f_ & 31) * 4;                         \
            CPA16(sb + (uint32_t)((bufV) + r_ * 136 + c_) * 4u,                 \
                  Vb_ + r_ * VD_ + c_, 16);                                     \
        }                                                                       \
        asm volatile("cp.async.commit_group;" ::: "memory");                    \
    } while (0)

    // Stage Q into buf1-K area, prefetch KV0 into buf0
    {
        const float* Qb = Qf + ((size_t)bh * S_ + q0) * QD_;
#pragma unroll
        for (int i = 0; i < 12; i++) {
            const int f = t + i * 256;
            const int r = f / 48, c = (f % 48) * 4;
            CPA16(sb + (uint32_t)(FK1 + r * 196 + c) * 4u, Qb + r * QD_ + c, 16);
        }
        asm volatile("cp.async.commit_group;" ::: "memory");
    }
    KV_LOAD(FK0, FV0, 0);
    asm volatile("cp.async.wait_group 1;" ::: "memory");
    __syncthreads();

    // Extract Q fragments (rows wr*16+g / +8)
    uint32_t qr[24][4];
    {
        const float* Qs = sm + FK1 + (wr * 16 + g) * 196 + tig;
#pragma unroll
        for (int ks = 0; ks < 24; ks++) {
            qr[ks][0] = __float_as_uint(Qs[ks * 8]);
            qr[ks][1] = __float_as_uint(Qs[ks * 8 + 8 * 196]);
            qr[ks][2] = __float_as_uint(Qs[ks * 8 + 4]);
            qr[ks][3] = __float_as_uint(Qs[ks * 8 + 8 * 196 + 4]);
        }
    }
    __syncthreads();
    if (qt >= 1) KV_LOAD(FK1, FV1, 1);

    float mi0 = -INFINITY, mi1 = -INFINITY, li0 = 0.f, li1 = 0.f;
    float acc[8][4];
#pragma unroll
    for (int nt = 0; nt < 8; nt++)
#pragma unroll
        for (int c = 0; c < 4; c++) acc[nt][c] = 0.f;

    const int row0 = wr * 16 + g;        // local row of c0/c1
    const int row1 = row0 + 8;

    for (int j = 0; j <= qt; ++j) {
        if (j < qt) asm volatile("cp.async.wait_group 1;" ::: "memory");
        else        asm volatile("cp.async.wait_group 0;" ::: "memory");
        __syncthreads();

        const int KB = (j & 1) ? FK1 : FK0;
        const int VB = (j & 1) ? FV1 : FV0;

        // ---- scores = Q @ K^T  (16x32 per warp) ----
        float s4[4][4];
#pragma unroll
        for (int nt = 0; nt < 4; nt++)
#pragma unroll
            for (int c = 0; c < 4; c++) s4[nt][c] = 0.f;

#pragma unroll
        for (int ks = 0; ks < 24; ks++) {
            uint32_t bf[4][2];
#pragma unroll
            for (int nt = 0; nt < 4; nt++) {
                const float* kp = sm + KB + (wc * 32 + nt * 8 + g) * 196 + ks * 8 + tig;
                bf[nt][0] = __float_as_uint(kp[0]);
                bf[nt][1] = __float_as_uint(kp[4]);
            }
#pragma unroll
            for (int nt = 0; nt < 4; nt++)
                MMA_TF32(s4[nt], qr[ks], bf[nt]);
        }

        // ---- causal mask (diagonal tile only; local coords valid: q0==j*64) ----
        if (j == qt) {
#pragma unroll
            for (int nt = 0; nt < 4; nt++) {
                const int col = wc * 32 + nt * 8 + tig * 2;
                if (col     > row0) s4[nt][0] = -1e30f;
                if (col + 1 > row0) s4[nt][1] = -1e30f;
                if (col     > row1) s4[nt][2] = -1e30f;
                if (col + 1 > row1) s4[nt][3] = -1e30f;
            }
        }

        // ---- row max (tig reduce -> smem combine across the 2 col-warps) ----
        float pm0 = fmaxf(fmaxf(s4[0][0], s4[0][1]), fmaxf(s4[1][0], s4[1][1]));
        pm0 = fmaxf(pm0, fmaxf(fmaxf(s4[2][0], s4[2][1]), fmaxf(s4[3][0], s4[3][1])));
        float pm1 = fmaxf(fmaxf(s4[0][2], s4[0][3]), fmaxf(s4[1][2], s4[1][3]));
        pm1 = fmaxf(pm1, fmaxf(fmaxf(s4[2][2], s4[2][3]), fmaxf(s4[3][2], s4[3][3])));
        pm0 = fmaxf(pm0, __shfl_xor_sync(0xffffffffu, pm0, 1));
        pm0 = fmaxf(pm0, __shfl_xor_sync(0xffffffffu, pm0, 2));
        pm1 = fmaxf(pm1, __shfl_xor_sync(0xffffffffu, pm1, 1));
        pm1 = fmaxf(pm1, __shfl_xor_sync(0xffffffffu, pm1, 2));
        if (tig == 0) {
            sm[FRM + wc * 64 + row0] = pm0;
            sm[FRM + wc * 64 + row1] = pm1;
        }
        __syncthreads();
        const float rm0 = fmaxf(sm[FRM + row0], sm[FRM + 64 + row0]);
        const float rm1 = fmaxf(sm[FRM + row1], sm[FRM + 64 + row1]);
        const float mn0 = fmaxf(mi0, rm0), mn1 = fmaxf(mi1, rm1);
        const float corr0 = __expf(mi0 - mn0), corr1 = __expf(mi1 - mn1);
        mi0 = mn0; mi1 = mn1;

        float rs0 = 0.f, rs1 = 0.f;
#pragma unroll
        for (int nt = 0; nt < 4; nt++) {
            s4[nt][0] = __expf(s4[nt][0] - mn0); rs0 += s4[nt][0];
            s4[nt][1] = __expf(s4[nt][1] - mn0); rs0 += s4[nt][1];
            s4[nt][2] = __expf(s4[nt][2] - mn1); rs1 += s4[nt][2];
            s4[nt][3] = __expf(s4[nt][3] - mn1); rs1 += s4[nt][3];
        }
        rs0 += __shfl_xor_sync(0xffffffffu, rs0, 1);
        rs0 += __shfl_xor_sync(0xffffffffu, rs0, 2);
        rs1 += __shfl_xor_sync(0xffffffffu, rs1, 1);
        rs1 += __shfl_xor_sync(0xffffffffu, rs1, 2);
        if (tig == 0) {
            sm[FRS + wc * 64 + row0] = rs0;
            sm[FRS + wc * 64 + row1] = rs1;
        }
        // ---- store P (tf32-rounded) ----
#pragma unroll
        for (int nt = 0; nt < 4; nt++) {
            const int col = wc * 32 + nt * 8 + tig * 2;
            *(float2*)&sm[FPS + row0 * 68 + col] =
                make_float2(to_tf32(s4[nt][0]), to_tf32(s4[nt][1]));
            *(float2*)&sm[FPS + row1 * 68 + col] =
                make_float2(to_tf32(s4[nt][2]), to_tf32(s4[nt][3]));
        }
        __syncthreads();

        li0 = li0 * corr0 + sm[FRS + row0] + sm[FRS + 64 + row0];
        li1 = li1 * corr1 + sm[FRS + row1] + sm[FRS + 64 + row1];
#pragma unroll
        for (int nt = 0; nt < 8; nt++) {
            acc[nt][0] *= corr0; acc[nt][1] *= corr0;
            acc[nt][2] *= corr1; acc[nt][3] *= corr1;
        }

        // ---- O += P @ V  (16x64 per warp) ----
#pragma unroll
        for (int ks = 0; ks < 8; ks++) {
            uint32_t a[4];
            const float* pp = sm + FPS + row0 * 68 + ks * 8 + tig;
            a[0] = __float_as_uint(pp[0]);
            a[1] = __float_as_uint(pp[8 * 68]);
            a[2] = __float_as_uint(pp[4]);
            a[3] = __float_as_uint(pp[8 * 68 + 4]);
#pragma unroll
            for (int nt = 0; nt < 8; nt++) {
                uint32_t bf[2];
                const float* vp = sm + VB + (ks * 8 + tig) * 136 + wc * 64 + nt * 8 + g;
                bf[0] = __float_as_uint(vp[0]);
                bf[1] = __float_as_uint(vp[4 * 136]);
                MMA_TF32(acc[nt], a, bf);
            }
        }
        __syncthreads();   // buf/Ps reads done before prefetch overwrites

        if (j + 2 <= qt) {
            if (j & 1) KV_LOAD(FK1, FV1, j + 2);
            else       KV_LOAD(FK0, FV0, j + 2);
        }
    }
#undef KV_LOAD

    // ---- epilogue ----
    const float linv0 = 1.0f / li0;
    const float linv1 = 1.0f / li1;
    const size_t r0g = (size_t)(b * S_ + q0 + row0) * (H_ * VD_) + h * VD_;
    const size_t r1g = (size_t)(b * S_ + q0 + row1) * (H_ * VD_) + h * VD_;
#pragma unroll
    for (int nt = 0; nt < 8; nt++) {
        const int col = wc * 64 + nt * 8 + tig * 2;
        *(float2*)&Out[r0g + col] =
            make_float2(to_tf32(acc[nt][0] * linv0), to_tf32(acc[nt][1] * linv0));
        *(float2*)&Out[r1g + col] =
            make_float2(to_tf32(acc[nt][2] * linv1), to_tf32(acc[nt][3] * linv1));
    }
}

// ---------------------------------------------------------------------------
// Launch
// ---------------------------------------------------------------------------
extern "C" void kernel_launch(void* const* d_in, const int* in_sizes, int n_in,
                              void* d_out, int out_size) {
    const float* x      = (const float*)d_in[0];
    const float* rope   = (const float*)d_in[1];
    const float* wq     = (const float*)d_in[2];
    const float* wkva   = (const float*)d_in[3];
    const float* norm_w = (const float*)d_in[4];
    const float* wkvb   = (const float*)d_in[5];
    const float* wo     = (const float*)d_in[6];
    float* out = (float*)d_out;

    float *p_q, *p_ckv, *p_norm, *p_kv, *p_qf, *p_kf, *p_v, *p_attn;
    float *p_xr, *p_wqr, *p_wkvar, *p_wkvbr, *p_wor;
    cudaGetSymbolAddress((void**)&p_q,     g_q);
    cudaGetSymbolAddress((void**)&p_ckv,   g_ckv);
    cudaGetSymbolAddress((void**)&p_norm,  g_norm);
    cudaGetSymbolAddress((void**)&p_kv,    g_kv);
    cudaGetSymbolAddress((void**)&p_qf,    g_qf);
    cudaGetSymbolAddress((void**)&p_kf,    g_kf);
    cudaGetSymbolAddress((void**)&p_v,     g_v);
    cudaGetSymbolAddress((void**)&p_attn,  g_attn);
    cudaGetSymbolAddress((void**)&p_xr,    g_xr);
    cudaGetSymbolAddress((void**)&p_wqr,   g_wqr);
    cudaGetSymbolAddress((void**)&p_wkvar, g_wkvar);
    cudaGetSymbolAddress((void**)&p_wkvbr, g_wkvbr);
    cudaGetSymbolAddress((void**)&p_wor,   g_wor);

    cudaFuncSetAttribute(mma_gemm, cudaFuncAttributeMaxDynamicSharedMemorySize,
                         MM_SMEM_BYTES);
    cudaFuncSetAttribute(flash_mma, cudaFuncAttributeMaxDynamicSharedMemorySize,
                         FL_SMEM_BYTES);

    // 0) round operands to tf32
    {
        int n;
        n = BS_ * DIM_ / 4;
        round_tf32_kernel<<<1024, 256>>>((const float4*)x, (float4*)p_xr, n);
        n = H_ * QD_ * DIM_ / 4;
        round_tf32_kernel<<<1024, 256>>>((const float4*)wq, (float4*)p_wqr, n);
        n = (KV_LORA_ + ROPE_) * DIM_ / 4;
        round_tf32_kernel<<<512, 256>>>((const float4*)wkva, (float4*)p_wkvar, n);
        n = H_ * 256 * KV_LORA_ / 4;
        round_tf32_kernel<<<512, 256>>>((const float4*)wkvb, (float4*)p_wkvbr, n);
        n = DIM_ * H_ * VD_ / 4;
        round_tf32_kernel<<<1024, 256>>>((const float4*)wo, (float4*)p_wor, n);
    }

    // 1) q = x @ wq^T
    mma_gemm<<<dim3(24, 32), 256, MM_SMEM_BYTES>>>(p_xr, p_wqr, p_q, H_ * QD_, DIM_);
    // 2) ckv = x @ wkva^T
    mma_gemm<<<dim3(5, 32), 256, MM_SMEM_BYTES>>>(p_xr, p_wkvar, p_ckv, KV_LORA_ + ROPE_, DIM_);
    // 3) RMSNorm
    rmsnorm_kernel<<<BS_, 128>>>(p_ckv, norm_w, p_norm);
    // 4) kv = norm @ wkvb^T
    mma_gemm<<<dim3(32, 32), 256, MM_SMEM_BYTES>>>(p_norm, p_wkvbr, p_kv, H_ * 256, KV_LORA_);
    // 5) RoPE + assemble
    assemble_kernel<<<BS_, 256>>>(p_q, p_ckv, p_kv, rope, p_qf, p_kf, p_v);
    // 6) tensor-core causal flash attention
    flash_mma<<<dim3(B_ * H_, S_ / 64), 256, FL_SMEM_BYTES>>>(p_qf, p_kf, p_v, p_attn);
    // 7) out = attn @ wo^T
    mma_gemm<<<dim3(16, 32), 256, MM_SMEM_BYTES>>>(p_attn, p_wor, out, DIM_, DIM_);
}

// round 10
// speedup vs baseline: 4.8955x; 1.0503x over previous
#include <cuda_runtime.h>
#include <cuda_bf16.h>
#include <math.h>
#include <stdint.h>

// Problem constants
#define B_       2
#define S_       2048
#define DIM_     2048
#define H_       16
#define KV_LORA_ 512
#define NOPE_    128
#define ROPE_    64
#define VD_      128
#define QD_      192
#define BS_      (B_ * S_)    // 4096
#define NQC_     3648         // fused q (3072) + ckv (576) output width

// ---------------------------------------------------------------------------
// Scratch
// ---------------------------------------------------------------------------
__device__ float g_qckv[BS_ * NQC_];           // fused q | ckv   (4096 x 3648)
__device__ float g_norm[BS_ * KV_LORA_];
__device__ float g_kv  [BS_ * H_ * (NOPE_ + VD_)];
__device__ float g_qf  [B_ * H_ * S_ * QD_];   // tf32-rounded, pre-scaled
__device__ float g_kf  [B_ * H_ * S_ * QD_];   // tf32-rounded
__device__ float g_v   [B_ * H_ * S_ * VD_];   // tf32-rounded
__device__ float g_attn[BS_ * H_ * VD_];       // tf32-rounded

__device__ float g_xr   [BS_ * DIM_];
__device__ float g_wqkva[NQC_ * DIM_];         // fused wq rows | wkva rows
__device__ float g_wkvbr[H_ * 256 * KV_LORA_];
__device__ float g_wor  [DIM_ * H_ * VD_];

// ---------------------------------------------------------------------------
// Helpers
// ---------------------------------------------------------------------------
__device__ __forceinline__ float to_tf32(float x) {
    uint32_t u;
    asm("cvt.rna.tf32.f32 %0, %1;" : "=r"(u) : "f"(x));
    return __uint_as_float(u);
}
__device__ __forceinline__ uint32_t smem_u32(const void* p) {
    uint32_t a;
    asm("{ .reg .u64 t; cvta.to.shared.u64 t, %1; cvt.u32.u64 %0, t; }"
        : "=r"(a) : "l"(p));
    return a;
}
#define CPA16(dst, src, sz) \
    asm volatile("cp.async.cg.shared.global [%0], [%1], 16, %2;" \
                 :: "r"(dst), "l"(src), "r"(sz) : "memory")
#define MMA_TF32(d, a, b)                                                     \
    asm volatile(                                                             \
        "mma.sync.aligned.m16n8k8.row.col.f32.tf32.tf32.f32 "                 \
        "{%0,%1,%2,%3}, {%4,%5,%6,%7}, {%8,%9}, {%0,%1,%2,%3};"               \
        : "+f"((d)[0]), "+f"((d)[1]), "+f"((d)[2]), "+f"((d)[3])              \
        : "r"((a)[0]), "r"((a)[1]), "r"((a)[2]), "r"((a)[3]),                 \
          "r"((b)[0]), "r"((b)[1]))

// ---------------------------------------------------------------------------
// tf32 mma.sync GEMM: C[M,N] = A[M,K] @ B[N,K]^T
// CTA tile 128x256, BK=32, 512 threads (16 warps, warp tile 64x32),
// 3-stage cp.async pipeline, single __syncthreads per K-iter.
// M mult 128, K mult 32, N guarded.
// ---------------------------------------------------------------------------
constexpr int MG_STR    = 36;
constexpr int MG_ABUF   = 128 * MG_STR;            // 4608 floats
constexpr int MG_BBUF   = 256 * MG_STR;            // 9216 floats
constexpr int MG_STAGE  = MG_ABUF + MG_BBUF;       // 13824 floats
constexpr unsigned MG_SMEM_BYTES = 3u * MG_STAGE * sizeof(float);  // 165888

__global__ __launch_bounds__(512, 1)
void mma_gemm(const float* __restrict__ A, const float* __restrict__ Bm,
              float* __restrict__ C, int N, int K) {
    extern __shared__ float sm[];
    const uint32_t sb = smem_u32(sm);

    const int t    = threadIdx.x;
    const int wid  = t >> 5;
    const int lane = t & 31;
    const int g    = lane >> 2;
    const int tig  = lane & 3;
    const int wm   = (wid & 1) * 64;
    const int wn   = (wid >> 1) * 32;        // 0..224
    const int m0   = blockIdx.y * 128;
    const int n0   = blockIdx.x * 256;
    const int NK   = K / 32;

    // load coordinates: A = 1024 float4 (2/thread), B = 2048 float4 (4/thread)
    int arow[2], ac4[2];
    const float* Asrc[2];
#pragma unroll
    for (int j = 0; j < 2; j++) {
        const int f = t + j * 512;
        arow[j] = f >> 3;
        ac4[j]  = f & 7;
        Asrc[j] = A + (size_t)(m0 + arow[j]) * K + ac4[j] * 4;
    }
    int brow[4], bc4[4], bsz[4];
    const float* Bsrc[4];
#pragma unroll
    for (int j = 0; j < 4; j++) {
        const int f = t + j * 512;
        brow[j] = f >> 3;               // 0..255
        bc4[j]  = f & 7;
        const int gr = n0 + brow[j];
        bsz[j]  = (gr < N) ? 16 : 0;
        Bsrc[j] = Bm + (size_t)((gr < N) ? gr : 0) * K + bc4[j] * 4;
    }

#define MG_LOAD(stg, kc)                                                        \
    do {                                                                        \
        const int k0_ = (kc) * 32;                                              \
        const uint32_t sA_ = sb + (uint32_t)((stg) * MG_STAGE) * 4u;            \
        const uint32_t sB_ = sA_ + (uint32_t)MG_ABUF * 4u;                      \
        _Pragma("unroll")                                                       \
        for (int j = 0; j < 2; j++)                                             \
            CPA16(sA_ + (uint32_t)(arow[j] * MG_STR + ac4[j] * 4) * 4u,         \
                  Asrc[j] + k0_, 16);                                           \
        _Pragma("unroll")                                                       \
        for (int j = 0; j < 4; j++)                                             \
            CPA16(sB_ + (uint32_t)(brow[j] * MG_STR + bc4[j] * 4) * 4u,         \
                  Bsrc[j] + k0_, bsz[j]);                                       \
    } while (0)

    float acc[4][4][4];
#pragma unroll
    for (int mi = 0; mi < 4; mi++)
#pragma unroll
        for (int ni = 0; ni < 4; ni++)
#pragma unroll
            for (int c = 0; c < 4; c++) acc[mi][ni][c] = 0.0f;

    MG_LOAD(0, 0);
    asm volatile("cp.async.commit_group;" ::: "memory");
    MG_LOAD(1, 1);
    asm volatile("cp.async.commit_group;" ::: "memory");

    int stg = 0;
    for (int i = 0; i < NK; ++i) {
        asm volatile("cp.async.wait_group 1;" ::: "memory");
        __syncthreads();

        const float* Ab = sm + stg * MG_STAGE;
        const float* Bb = Ab + MG_ABUF;
#pragma unroll
        for (int ks = 0; ks < 4; ks++) {
            const int k0 = ks * 8;
            uint32_t a[4][4], b[4][2];
#pragma unroll
            for (int mi = 0; mi < 4; mi++) {
                const float* ap = Ab + (wm + mi * 16 + g) * MG_STR + k0 + tig;
                a[mi][0] = __float_as_uint(ap[0]);
                a[mi][1] = __float_as_uint(ap[8 * MG_STR]);
                a[mi][2] = __float_as_uint(ap[4]);
                a[mi][3] = __float_as_uint(ap[8 * MG_STR + 4]);
            }
#pragma unroll
            for (int ni = 0; ni < 4; ni++) {
                const float* bp = Bb + (wn + ni * 8 + g) * MG_STR + k0 + tig;
                b[ni][0] = __float_as_uint(bp[0]);
                b[ni][1] = __float_as_uint(bp[4]);
            }
#pragma unroll
            for (int mi = 0; mi < 4; mi++)
#pragma unroll
                for (int ni = 0; ni < 4; ni++)
                    MMA_TF32(acc[mi][ni], a[mi], b[ni]);
        }

        if (i + 2 < NK) MG_LOAD((stg + 2) % 3, i + 2);
        asm volatile("cp.async.commit_group;" ::: "memory");
        stg = (stg + 1) % 3;
    }
#undef MG_LOAD

#pragma unroll
    for (int mi = 0; mi < 4; mi++) {
        const int rr = m0 + wm + mi * 16 + g;
#pragma unroll
        for (int ni = 0; ni < 4; ni++) {
            const int cc = n0 + wn + ni * 8 + tig * 2;
            if (cc < N) {
                float2 v0 = make_float2(acc[mi][ni][0], acc[mi][ni][1]);
                float2 v1 = make_float2(acc[mi][ni][2], acc[mi][ni][3]);
                *(float2*)&C[(size_t)rr * N + cc]       = v0;
                *(float2*)&C[(size_t)(rr + 8) * N + cc] = v1;
            }
        }
    }
}

// ---------------------------------------------------------------------------
// tf32 rounding pass
// ---------------------------------------------------------------------------
__global__ __launch_bounds__(256) void round_tf32_kernel(const float4* __restrict__ src,
                                                         float4* __restrict__ dst, int n4) {
    for (int i = blockIdx.x * 256 + threadIdx.x; i < n4; i += gridDim.x * 256) {
        float4 v = src[i];
        v.x = to_tf32(v.x); v.y = to_tf32(v.y);
        v.z = to_tf32(v.z); v.w = to_tf32(v.w);
        dst[i] = v;
    }
}

// ---------------------------------------------------------------------------
// RMSNorm over qckv[row, 3072:3584]; tf32-rounded out
// ---------------------------------------------------------------------------
__global__ __launch_bounds__(128) void rmsnorm_kernel(const float* __restrict__ qckv,
                                                      const float* __restrict__ w,
                                                      float* __restrict__ outp) {
    const int row = blockIdx.x;
    const int t   = threadIdx.x;
    const float* xr = qckv + (size_t)row * NQC_ + H_ * QD_;
    float v[4];
    float s = 0.f;
#pragma unroll
    for (int i = 0; i < 4; i++) { v[i] = xr[t + i * 128]; s += v[i] * v[i]; }
#pragma unroll
    for (int m = 16; m >= 1; m >>= 1) s += __shfl_xor_sync(0xffffffffu, s, m);
    __shared__ float ws[4];
    if ((t & 31) == 0) ws[t >> 5] = s;
    __syncthreads();
    s = ws[0] + ws[1] + ws[2] + ws[3];
    const float inv = rsqrtf(s * (1.0f / (float)KV_LORA_) + 1e-6f);
    float* orow = outp + (size_t)row * KV_LORA_;
#pragma unroll
    for (int i = 0; i < 4; i++) orow[t + i * 128] = to_tf32(v[i] * inv * w[t + i * 128]);
}

// ---------------------------------------------------------------------------
// RoPE + assembly from fused qckv; outputs tf32-rounded
// ---------------------------------------------------------------------------
__global__ __launch_bounds__(256) void assemble_kernel(const float* __restrict__ qckv,
                                                       const float* __restrict__ kv,
                                                       const float* __restrict__ rope,
                                                       float* __restrict__ qf,
                                                       float* __restrict__ kf,
                                                       float* __restrict__ v) {
    const int row = blockIdx.x;
    const int s   = row & (S_ - 1);
    const int b   = row >> 11;
    const int t   = threadIdx.x;

    __shared__ float cs[64], sn[64], kr[64];
    if (t < 64) {
        cs[t] = rope[(size_t)s * 128 + t];
        sn[t] = rope[(size_t)s * 128 + 64 + t];
    }
    __syncthreads();
    if (t < 64) {
        const float* cr = qckv + (size_t)row * NQC_ + H_ * QD_ + KV_LORA_;
        float k0  = cr[t];
        float rot = (t < 32) ? -cr[t + 32] : cr[t - 32];
        kr[t] = k0 * cs[t] + rot * sn[t];
    }
    __syncthreads();

    const float scale = rsqrtf((float)QD_);
    for (int idx = t; idx < H_ * QD_; idx += 256) {
        const int h = idx / QD_;
        const int d = idx - h * QD_;
        const size_t dst = ((size_t)(b * H_ + h) * S_ + s) * QD_ + d;
        const float* qrow = qckv + (size_t)row * NQC_ + h * QD_;
        float qv;
        if (d < NOPE_) {
            qv = qrow[d];
        } else {
            const int r   = d - NOPE_;
            float q1  = qrow[NOPE_ + r];
            float rot = (r < 32) ? -qrow[NOPE_ + r + 32] : qrow[NOPE_ + r - 32];
            qv = q1 * cs[r] + rot * sn[r];
        }
        qf[dst] = to_tf32(qv * scale);
        float kvv;
        if (d < NOPE_) kvv = kv[(size_t)row * (H_ * 256) + h * 256 + d];
        else           kvv = kr[d - NOPE_];
        kf[dst] = to_tf32(kvv);
    }
    for (int idx = t; idx < H_ * VD_; idx += 256) {
        const int h  = idx >> 7;
        const int dv = idx & 127;
        v[((size_t)(b * H_ + h) * S_ + s) * VD_ + dv] =
            to_tf32(kv[(size_t)row * (H_ * 256) + h * 256 + NOPE_ + dv]);
    }
}

// ---------------------------------------------------------------------------
// Tensor-core causal flash attention (tf32 mma.sync) -- unchanged from R9
// ---------------------------------------------------------------------------
constexpr int FK0 = 0;
constexpr int FV0 = 12544;
constexpr int FK1 = 21248;
constexpr int FV1 = 33792;
constexpr int FPS = 42496;
constexpr int FRM = 46848;
constexpr int FRS = 46976;
constexpr unsigned FL_SMEM_BYTES = 47104u * 4u;

__global__ __launch_bounds__(256, 1)
void flash_mma(const float* __restrict__ Qf, const float* __restrict__ Kf,
               const float* __restrict__ Vf, float* __restrict__ Out) {
    extern __shared__ float sm[];
    const uint32_t sb = smem_u32(sm);

    const int t    = threadIdx.x;
    const int wid  = t >> 5;
    const int lane = t & 31;
    const int g    = lane >> 2;
    const int tig  = lane & 3;
    const int wr   = wid >> 1;
    const int wc   = wid & 1;
    const int bh   = blockIdx.x;
    const int qt   = (int)gridDim.y - 1 - (int)blockIdx.y;
    const int q0   = qt * 64;
    const int b    = bh >> 4, h = bh & 15;

    const float* Kbase = Kf + (size_t)bh * S_ * QD_;
    const float* Vbase = Vf + (size_t)bh * S_ * VD_;

#define KV_LOAD(bufK, bufV, jj)                                                 \
    do {                                                                        \
        const float* Kb_ = Kbase + (size_t)(jj) * 64 * QD_;                     \
        const float* Vb_ = Vbase + (size_t)(jj) * 64 * VD_;                     \
        _Pragma("unroll")                                                       \
        for (int i_ = 0; i_ < 12; i_++) {                                       \
            const int f_ = t + i_ * 256;                                        \
            const int r_ = f_ / 48, c_ = (f_ % 48) * 4;                         \
            CPA16(sb + (uint32_t)((bufK) + r_ * 196 + c_) * 4u,                 \
                  Kb_ + r_ * QD_ + c_, 16);                                     \
        }                                                                       \
        _Pragma("unroll")                                                       \
        for (int i_ = 0; i_ < 8; i_++) {                                        \
            const int f_ = t + i_ * 256;                                        \
            const int r_ = f_ >> 5, c_ = (f_ & 31) * 4;                         \
            CPA16(sb + (uint32_t)((bufV) + r_ * 136 + c_) * 4u,                 \
                  Vb_ + r_ * VD_ + c_, 16);                                     \
        }                                                                       \
        asm volatile("cp.async.commit_group;" ::: "memory");                    \
    } while (0)

    {
        const float* Qb = Qf + ((size_t)bh * S_ + q0) * QD_;
#pragma unroll
        for (int i = 0; i < 12; i++) {
            const int f = t + i * 256;
            const int r = f / 48, c = (f % 48) * 4;
            CPA16(sb + (uint32_t)(FK1 + r * 196 + c) * 4u, Qb + r * QD_ + c, 16);
        }
        asm volatile("cp.async.commit_group;" ::: "memory");
    }
    KV_LOAD(FK0, FV0, 0);
    asm volatile("cp.async.wait_group 1;" ::: "memory");
    __syncthreads();

    uint32_t qr[24][4];
    {
        const float* Qs = sm + FK1 + (wr * 16 + g) * 196 + tig;
#pragma unroll
        for (int ks = 0; ks < 24; ks++) {
            qr[ks][0] = __float_as_uint(Qs[ks * 8]);
            qr[ks][1] = __float_as_uint(Qs[ks * 8 + 8 * 196]);
            qr[ks][2] = __float_as_uint(Qs[ks * 8 + 4]);
            qr[ks][3] = __float_as_uint(Qs[ks * 8 + 8 * 196 + 4]);
        }
    }
    __syncthreads();
    if (qt >= 1) KV_LOAD(FK1, FV1, 1);

    float mi0 = -INFINITY, mi1 = -INFINITY, li0 = 0.f, li1 = 0.f;
    float acc[8][4];
#pragma unroll
    for (int nt = 0; nt < 8; nt++)
#pragma unroll
        for (int c = 0; c < 4; c++) acc[nt][c] = 0.f;

    const int row0 = wr * 16 + g;
    const int row1 = row0 + 8;

    for (int j = 0; j <= qt; ++j) {
        if (j < qt) asm volatile("cp.async.wait_group 1;" ::: "memory");
        else        asm volatile("cp.async.wait_group 0;" ::: "memory");
        __syncthreads();

        const int KB = (j & 1) ? FK1 : FK0;
        const int VB = (j & 1) ? FV1 : FV0;

        float s4[4][4];
#pragma unroll
        for (int nt = 0; nt < 4; nt++)
#pragma unroll
            for (int c = 0; c < 4; c++) s4[nt][c] = 0.f;

#pragma unroll
        for (int ks = 0; ks < 24; ks++) {
            uint32_t bf[4][2];
#pragma unroll
            for (int nt = 0; nt < 4; nt++) {
                const float* kp = sm + KB + (wc * 32 + nt * 8 + g) * 196 + ks * 8 + tig;
                bf[nt][0] = __float_as_uint(kp[0]);
                bf[nt][1] = __float_as_uint(kp[4]);
            }
#pragma unroll
            for (int nt = 0; nt < 4; nt++)
                MMA_TF32(s4[nt], qr[ks], bf[nt]);
        }

        if (j == qt) {
#pragma unroll
            for (int nt = 0; nt < 4; nt++) {
                const int col = wc * 32 + nt * 8 + tig * 2;
                if (col     > row0) s4[nt][0] = -1e30f;
                if (col + 1 > row0) s4[nt][1] = -1e30f;
                if (col     > row1) s4[nt][2] = -1e30f;
                if (col + 1 > row1) s4[nt][3] = -1e30f;
            }
        }

        float pm0 = fmaxf(fmaxf(s4[0][0], s4[0][1]), fmaxf(s4[1][0], s4[1][1]));
        pm0 = fmaxf(pm0, fmaxf(fmaxf(s4[2][0], s4[2][1]), fmaxf(s4[3][0], s4[3][1])));
        float pm1 = fmaxf(fmaxf(s4[0][2], s4[0][3]), fmaxf(s4[1][2], s4[1][3]));
        pm1 = fmaxf(pm1, fmaxf(fmaxf(s4[2][2], s4[2][3]), fmaxf(s4[3][2], s4[3][3])));
        pm0 = fmaxf(pm0, __shfl_xor_sync(0xffffffffu, pm0, 1));
        pm0 = fmaxf(pm0, __shfl_xor_sync(0xffffffffu, pm0, 2));
        pm1 = fmaxf(pm1, __shfl_xor_sync(0xffffffffu, pm1, 1));
        pm1 = fmaxf(pm1, __shfl_xor_sync(0xffffffffu, pm1, 2));
        if (tig == 0) {
            sm[FRM + wc * 64 + row0] = pm0;
            sm[FRM + wc * 64 + row1] = pm1;
        }
        __syncthreads();
        const float rm0 = fmaxf(sm[FRM + row0], sm[FRM + 64 + row0]);
        const float rm1 = fmaxf(sm[FRM + row1], sm[FRM + 64 + row1]);
        const float mn0 = fmaxf(mi0, rm0), mn1 = fmaxf(mi1, rm1);
        const float corr0 = __expf(mi0 - mn0), corr1 = __expf(mi1 - mn1);
        mi0 = mn0; mi1 = mn1;

        float rs0 = 0.f, rs1 = 0.f;
#pragma unroll
        for (int nt = 0; nt < 4; nt++) {
            s4[nt][0] = __expf(s4[nt][0] - mn0); rs0 += s4[nt][0];
            s4[nt][1] = __expf(s4[nt][1] - mn0); rs0 += s4[nt][1];
            s4[nt][2] = __expf(s4[nt][2] - mn1); rs1 += s4[nt][2];
            s4[nt][3] = __expf(s4[nt][3] - mn1); rs1 += s4[nt][3];
        }
        rs0 += __shfl_xor_sync(0xffffffffu, rs0, 1);
        rs0 += __shfl_xor_sync(0xffffffffu, rs0, 2);
        rs1 += __shfl_xor_sync(0xffffffffu, rs1, 1);
        rs1 += __shfl_xor_sync(0xffffffffu, rs1, 2);
        if (tig == 0) {
            sm[FRS + wc * 64 + row0] = rs0;
            sm[FRS + wc * 64 + row1] = rs1;
        }
#pragma unroll
        for (int nt = 0; nt < 4; nt++) {
            const int col = wc * 32 + nt * 8 + tig * 2;
            *(float2*)&sm[FPS + row0 * 68 + col] =
                make_float2(to_tf32(s4[nt][0]), to_tf32(s4[nt][1]));
            *(float2*)&sm[FPS + row1 * 68 + col] =
                make_float2(to_tf32(s4[nt][2]), to_tf32(s4[nt][3]));
        }
        __syncthreads();

        li0 = li0 * corr0 + sm[FRS + row0] + sm[FRS + 64 + row0];
        li1 = li1 * corr1 + sm[FRS + row1] + sm[FRS + 64 + row1];
#pragma unroll
        for (int nt = 0; nt < 8; nt++) {
            acc[nt][0] *= corr0; acc[nt][1] *= corr0;
            acc[nt][2] *= corr1; acc[nt][3] *= corr1;
        }

#pragma unroll
        for (int ks = 0; ks < 8; ks++) {
            uint32_t a[4];
            const float* pp = sm + FPS + row0 * 68 + ks * 8 + tig;
            a[0] = __float_as_uint(pp[0]);
            a[1] = __float_as_uint(pp[8 * 68]);
            a[2] = __float_as_uint(pp[4]);
            a[3] = __float_as_uint(pp[8 * 68 + 4]);
#pragma unroll
            for (int nt = 0; nt < 8; nt++) {
                uint32_t bf[2];
                const float* vp = sm + VB + (ks * 8 + tig) * 136 + wc * 64 + nt * 8 + g;
                bf[0] = __float_as_uint(vp[0]);
                bf[1] = __float_as_uint(vp[4 * 136]);
                MMA_TF32(acc[nt], a, bf);
            }
        }
        __syncthreads();

        if (j + 2 <= qt) {
            if (j & 1) KV_LOAD(FK1, FV1, j + 2);
            else       KV_LOAD(FK0, FV0, j + 2);
        }
    }
#undef KV_LOAD

    const float linv0 = 1.0f / li0;
    const float linv1 = 1.0f / li1;
    const size_t r0g = (size_t)(b * S_ + q0 + row0) * (H_ * VD_) + h * VD_;
    const size_t r1g = (size_t)(b * S_ + q0 + row1) * (H_ * VD_) + h * VD_;
#pragma unroll
    for (int nt = 0; nt < 8; nt++) {
        const int col = wc * 64 + nt * 8 + tig * 2;
        *(float2*)&Out[r0g + col] =
            make_float2(to_tf32(acc[nt][0] * linv0), to_tf32(acc[nt][1] * linv0));
        *(float2*)&Out[r1g + col] =
            make_float2(to_tf32(acc[nt][2] * linv1), to_tf32(acc[nt][3] * linv1));
    }
}

// ---------------------------------------------------------------------------
// Launch
// ---------------------------------------------------------------------------
extern "C" void kernel_launch(void* const* d_in, const int* in_sizes, int n_in,
                              void* d_out, int out_size) {
    const float* x      = (const float*)d_in[0];
    const float* rope   = (const float*)d_in[1];
    const float* wq     = (const float*)d_in[2];
    const float* wkva   = (const float*)d_in[3];
    const float* norm_w = (const float*)d_in[4];
    const float* wkvb   = (const float*)d_in[5];
    const float* wo     = (const float*)d_in[6];
    float* out = (float*)d_out;

    float *p_qckv, *p_norm, *p_kv, *p_qf, *p_kf, *p_v, *p_attn;
    float *p_xr, *p_wqkva, *p_wkvbr, *p_wor;
    cudaGetSymbolAddress((void**)&p_qckv,  g_qckv);
    cudaGetSymbolAddress((void**)&p_norm,  g_norm);
    cudaGetSymbolAddress((void**)&p_kv,    g_kv);
    cudaGetSymbolAddress((void**)&p_qf,    g_qf);
    cudaGetSymbolAddress((void**)&p_kf,    g_kf);
    cudaGetSymbolAddress((void**)&p_v,     g_v);
    cudaGetSymbolAddress((void**)&p_attn,  g_attn);
    cudaGetSymbolAddress((void**)&p_xr,    g_xr);
    cudaGetSymbolAddress((void**)&p_wqkva, g_wqkva);
    cudaGetSymbolAddress((void**)&p_wkvbr, g_wkvbr);
    cudaGetSymbolAddress((void**)&p_wor,   g_wor);

    cudaFuncSetAttribute(mma_gemm, cudaFuncAttributeMaxDynamicSharedMemorySize,
                         MG_SMEM_BYTES);
    cudaFuncSetAttribute(flash_mma, cudaFuncAttributeMaxDynamicSharedMemorySize,
                         FL_SMEM_BYTES);

    // 0) round operands to tf32 (wq & wkva concatenated into fused B)
    {
        int n;
        n = BS_ * DIM_ / 4;
        round_tf32_kernel<<<1024, 256>>>((const float4*)x, (float4*)p_xr, n);
        n = H_ * QD_ * DIM_ / 4;
        round_tf32_kernel<<<1024, 256>>>((const float4*)wq, (float4*)p_wqkva, n);
        n = (KV_LORA_ + ROPE_) * DIM_ / 4;
        round_tf32_kernel<<<512, 256>>>((const float4*)wkva,
                                        (float4*)(p_wqkva + (size_t)H_ * QD_ * DIM_), n);
        n = H_ * 256 * KV_LORA_ / 4;
        round_tf32_kernel<<<512, 256>>>((const float4*)wkvb, (float4*)p_wkvbr, n);
        n = DIM_ * H_ * VD_ / 4;
        round_tf32_kernel<<<1024, 256>>>((const float4*)wo, (float4*)p_wor, n);
    }

    // 1) qckv = x @ [wq; wkva]^T   [4096, 3648]
    mma_gemm<<<dim3(15, 32), 512, MG_SMEM_BYTES>>>(p_xr, p_wqkva, p_qckv, NQC_, DIM_);
    // 2) RMSNorm
    rmsnorm_kernel<<<BS_, 128>>>(p_qckv, norm_w, p_norm);
    // 3) kv = norm @ wkvb^T        [4096, 4096]
    mma_gemm<<<dim3(16, 32), 512, MG_SMEM_BYTES>>>(p_norm, p_wkvbr, p_kv, H_ * 256, KV_LORA_);
    // 4) RoPE + assemble
    assemble_kernel<<<BS_, 256>>>(p_qckv, p_kv, rope, p_qf, p_kf, p_v);
    // 5) tensor-core causal flash attention
    flash_mma<<<dim3(B_ * H_, S_ / 64), 256, FL_SMEM_BYTES>>>(p_qf, p_kf, p_v, p_attn);
    // 6) out = attn @ wo^T         [4096, 2048]
    mma_gemm<<<dim3(8, 32), 512, MG_SMEM_BYTES>>>(p_attn, p_wor, out, DIM_, DIM_);
}

// round 12
// speedup vs baseline: 5.0963x; 1.0410x over previous
#include <cuda_runtime.h>
#include <cuda_bf16.h>
#include <math.h>
#include <stdint.h>

// Problem constants
#define B_       2
#define S_       2048
#define DIM_     2048
#define H_       16
#define KV_LORA_ 512
#define NOPE_    128
#define ROPE_    64
#define VD_      128
#define QD_      192
#define BS_      (B_ * S_)    // 4096
#define NQC_     3648         // fused q (3072) + ckv (576) output width

// ---------------------------------------------------------------------------
// Scratch
// ---------------------------------------------------------------------------
__device__ float g_qckv[BS_ * NQC_];           // fused q | ckv   (4096 x 3648)
__device__ float g_norm[BS_ * KV_LORA_];
__device__ float g_kv  [BS_ * H_ * (NOPE_ + VD_)];
__device__ float g_qf  [B_ * H_ * S_ * QD_];   // tf32-rounded, pre-scaled
__device__ float g_kf  [B_ * H_ * S_ * QD_];   // tf32-rounded
__device__ float g_v   [B_ * H_ * S_ * VD_];   // tf32-rounded
__device__ float g_attn[BS_ * H_ * VD_];       // tf32-rounded

__device__ float g_xr   [BS_ * DIM_];
__device__ float g_wqkva[NQC_ * DIM_];         // fused wq rows | wkva rows
__device__ float g_wkvbr[H_ * 256 * KV_LORA_];
__device__ float g_wor  [DIM_ * H_ * VD_];

// ---------------------------------------------------------------------------
// Helpers
// ---------------------------------------------------------------------------
__device__ __forceinline__ float to_tf32(float x) {
    uint32_t u;
    asm("cvt.rna.tf32.f32 %0, %1;" : "=r"(u) : "f"(x));
    return __uint_as_float(u);
}
__device__ __forceinline__ uint32_t smem_u32(const void* p) {
    uint32_t a;
    asm("{ .reg .u64 t; cvta.to.shared.u64 t, %1; cvt.u32.u64 %0, t; }"
        : "=r"(a) : "l"(p));
    return a;
}
#define CPA16(dst, src, sz) \
    asm volatile("cp.async.cg.shared.global [%0], [%1], 16, %2;" \
                 :: "r"(dst), "l"(src), "r"(sz) : "memory")
#define MMA_TF32(d, a, b)                                                     \
    asm volatile(                                                             \
        "mma.sync.aligned.m16n8k8.row.col.f32.tf32.tf32.f32 "                 \
        "{%0,%1,%2,%3}, {%4,%5,%6,%7}, {%8,%9}, {%0,%1,%2,%3};"               \
        : "+f"((d)[0]), "+f"((d)[1]), "+f"((d)[2]), "+f"((d)[3])              \
        : "r"((a)[0]), "r"((a)[1]), "r"((a)[2]), "r"((a)[3]),                 \
          "r"((b)[0]), "r"((b)[1]))

// ---------------------------------------------------------------------------
// tf32 mma.sync GEMM: C[M,N] = A[M,K] @ B[N,K]^T
// CTA tile 128x256, BK=32, 256 threads = 8 warps, warp tile 64x64,
// 3-stage cp.async pipeline. 1.0 LDS per MMA (issue-balanced).
// M mult 128, K mult 32, N guarded.
// ---------------------------------------------------------------------------
constexpr int MG_STR    = 36;
constexpr int MG_ABUF   = 128 * MG_STR;            // 4608 floats
constexpr int MG_BBUF   = 256 * MG_STR;            // 9216 floats
constexpr int MG_STAGE  = MG_ABUF + MG_BBUF;       // 13824 floats
constexpr unsigned MG_SMEM_BYTES = 3u * MG_STAGE * sizeof(float);  // 165888

__global__ __launch_bounds__(256, 1)
void mma_gemm(const float* __restrict__ A, const float* __restrict__ Bm,
              float* __restrict__ C, int N, int K) {
    extern __shared__ float sm[];
    const uint32_t sb = smem_u32(sm);

    const int t    = threadIdx.x;
    const int wid  = t >> 5;
    const int lane = t & 31;
    const int g    = lane >> 2;
    const int tig  = lane & 3;
    const int wm   = (wid & 1) * 64;
    const int wn   = (wid >> 1) * 64;        // 0..192
    const int m0   = blockIdx.y * 128;
    const int n0   = blockIdx.x * 256;
    const int NK   = K / 32;

    // load coordinates: A = 1024 float4 (4/thread), B = 2048 float4 (8/thread)
    int arow[4], ac4[4];
    const float* Asrc[4];
#pragma unroll
    for (int j = 0; j < 4; j++) {
        const int f = t + j * 256;
        arow[j] = f >> 3;
        ac4[j]  = f & 7;
        Asrc[j] = A + (size_t)(m0 + arow[j]) * K + ac4[j] * 4;
    }
    int brow[8], bc4[8], bsz[8];
    const float* Bsrc[8];
#pragma unroll
    for (int j = 0; j < 8; j++) {
        const int f = t + j * 256;
        brow[j] = f >> 3;               // 0..255
        bc4[j]  = f & 7;
        const int gr = n0 + brow[j];
        bsz[j]  = (gr < N) ? 16 : 0;
        Bsrc[j] = Bm + (size_t)((gr < N) ? gr : 0) * K + bc4[j] * 4;
    }

#define MG_LOAD(stg, kc)                                                        \
    do {                                                                        \
        const int k0_ = (kc) * 32;                                              \
        const uint32_t sA_ = sb + (uint32_t)((stg) * MG_STAGE) * 4u;            \
        const uint32_t sB_ = sA_ + (uint32_t)MG_ABUF * 4u;                      \
        _Pragma("unroll")                                                       \
        for (int j = 0; j < 4; j++)                                             \
            CPA16(sA_ + (uint32_t)(arow[j] * MG_STR + ac4[j] * 4) * 4u,         \
                  Asrc[j] + k0_, 16);                                           \
        _Pragma("unroll")                                                       \
        for (int j = 0; j < 8; j++)                                             \
            CPA16(sB_ + (uint32_t)(brow[j] * MG_STR + bc4[j] * 4) * 4u,         \
                  Bsrc[j] + k0_, bsz[j]);                                       \
    } while (0)

    float acc[4][8][4];
#pragma unroll
    for (int mi = 0; mi < 4; mi++)
#pragma unroll
        for (int ni = 0; ni < 8; ni++)
#pragma unroll
            for (int c = 0; c < 4; c++) acc[mi][ni][c] = 0.0f;

    MG_LOAD(0, 0);
    asm volatile("cp.async.commit_group;" ::: "memory");
    MG_LOAD(1, 1);
    asm volatile("cp.async.commit_group;" ::: "memory");

    int stg = 0;
    for (int i = 0; i < NK; ++i) {
        asm volatile("cp.async.wait_group 1;" ::: "memory");
        __syncthreads();

        const float* Ab = sm + stg * MG_STAGE;
        const float* Bb = Ab + MG_ABUF;
#pragma unroll
        for (int ks = 0; ks < 4; ks++) {
            const int k0 = ks * 8;
            uint32_t a[4][4], b[8][2];
#pragma unroll
            for (int mi = 0; mi < 4; mi++) {
                const float* ap = Ab + (wm + mi * 16 + g) * MG_STR + k0 + tig;
                a[mi][0] = __float_as_uint(ap[0]);
                a[mi][1] = __float_as_uint(ap[8 * MG_STR]);
                a[mi][2] = __float_as_uint(ap[4]);
                a[mi][3] = __float_as_uint(ap[8 * MG_STR + 4]);
            }
#pragma unroll
            for (int ni = 0; ni < 8; ni++) {
                const float* bp = Bb + (wn + ni * 8 + g) * MG_STR + k0 + tig;
                b[ni][0] = __float_as_uint(bp[0]);
                b[ni][1] = __float_as_uint(bp[4]);
            }
#pragma unroll
            for (int mi = 0; mi < 4; mi++)
#pragma unroll
                for (int ni = 0; ni < 8; ni++)
                    MMA_TF32(acc[mi][ni], a[mi], b[ni]);
        }

        if (i + 2 < NK) MG_LOAD((stg + 2) % 3, i + 2);
        asm volatile("cp.async.commit_group;" ::: "memory");
        stg = (stg + 1) % 3;
    }
#undef MG_LOAD

#pragma unroll
    for (int mi = 0; mi < 4; mi++) {
        const int rr = m0 + wm + mi * 16 + g;
#pragma unroll
        for (int ni = 0; ni < 8; ni++) {
            const int cc = n0 + wn + ni * 8 + tig * 2;
            if (cc < N) {
                float2 v0 = make_float2(acc[mi][ni][0], acc[mi][ni][1]);
                float2 v1 = make_float2(acc[mi][ni][2], acc[mi][ni][3]);
                *(float2*)&C[(size_t)rr * N + cc]       = v0;
                *(float2*)&C[(size_t)(rr + 8) * N + cc] = v1;
            }
        }
    }
}

// ---------------------------------------------------------------------------
// tf32 rounding pass
// ---------------------------------------------------------------------------
__global__ __launch_bounds__(256) void round_tf32_kernel(const float4* __restrict__ src,
                                                         float4* __restrict__ dst, int n4) {
    for (int i = blockIdx.x * 256 + threadIdx.x; i < n4; i += gridDim.x * 256) {
        float4 v = src[i];
        v.x = to_tf32(v.x); v.y = to_tf32(v.y);
        v.z = to_tf32(v.z); v.w = to_tf32(v.w);
        dst[i] = v;
    }
}

// ---------------------------------------------------------------------------
// RMSNorm over qckv[row, 3072:3584]; tf32-rounded out
// ---------------------------------------------------------------------------
__global__ __launch_bounds__(128) void rmsnorm_kernel(const float* __restrict__ qckv,
                                                      const float* __restrict__ w,
                                                      float* __restrict__ outp) {
    const int row = blockIdx.x;
    const int t   = threadIdx.x;
    const float* xr = qckv + (size_t)row * NQC_ + H_ * QD_;
    float v[4];
    float s = 0.f;
#pragma unroll
    for (int i = 0; i < 4; i++) { v[i] = xr[t + i * 128]; s += v[i] * v[i]; }
#pragma unroll
    for (int m = 16; m >= 1; m >>= 1) s += __shfl_xor_sync(0xffffffffu, s, m);
    __shared__ float ws[4];
    if ((t & 31) == 0) ws[t >> 5] = s;
    __syncthreads();
    s = ws[0] + ws[1] + ws[2] + ws[3];
    const float inv = rsqrtf(s * (1.0f / (float)KV_LORA_) + 1e-6f);
    float* orow = outp + (size_t)row * KV_LORA_;
#pragma unroll
    for (int i = 0; i < 4; i++) orow[t + i * 128] = to_tf32(v[i] * inv * w[t + i * 128]);
}

// ---------------------------------------------------------------------------
// RoPE + assembly from fused qckv; outputs tf32-rounded
// ---------------------------------------------------------------------------
__global__ __launch_bounds__(256) void assemble_kernel(const float* __restrict__ qckv,
                                                       const float* __restrict__ kv,
                                                       const float* __restrict__ rope,
                                                       float* __restrict__ qf,
                                                       float* __restrict__ kf,
                                                       float* __restrict__ v) {
    const int row = blockIdx.x;
    const int s   = row & (S_ - 1);
    const int b   = row >> 11;
    const int t   = threadIdx.x;

    __shared__ float cs[64], sn[64], kr[64];
    if (t < 64) {
        cs[t] = rope[(size_t)s * 128 + t];
        sn[t] = rope[(size_t)s * 128 + 64 + t];
    }
    __syncthreads();
    if (t < 64) {
        const float* cr = qckv + (size_t)row * NQC_ + H_ * QD_ + KV_LORA_;
        float k0  = cr[t];
        float rot = (t < 32) ? -cr[t + 32] : cr[t - 32];
        kr[t] = k0 * cs[t] + rot * sn[t];
    }
    __syncthreads();

    const float scale = rsqrtf((float)QD_);
    for (int idx = t; idx < H_ * QD_; idx += 256) {
        const int h = idx / QD_;
        const int d = idx - h * QD_;
        const size_t dst = ((size_t)(b * H_ + h) * S_ + s) * QD_ + d;
        const float* qrow = qckv + (size_t)row * NQC_ + h * QD_;
        float qv;
        if (d < NOPE_) {
            qv = qrow[d];
        } else {
            const int r   = d - NOPE_;
            float q1  = qrow[NOPE_ + r];
            float rot = (r < 32) ? -qrow[NOPE_ + r + 32] : qrow[NOPE_ + r - 32];
            qv = q1 * cs[r] + rot * sn[r];
        }
        qf[dst] = to_tf32(qv * scale);
        float kvv;
        if (d < NOPE_) kvv = kv[(size_t)row * (H_ * 256) + h * 256 + d];
        else           kvv = kr[d - NOPE_];
        kf[dst] = to_tf32(kvv);
    }
    for (int idx = t; idx < H_ * VD_; idx += 256) {
        const int h  = idx >> 7;
        const int dv = idx & 127;
        v[((size_t)(b * H_ + h) * S_ + s) * VD_ + dv] =
            to_tf32(kv[(size_t)row * (H_ * 256) + h * 256 + NOPE_ + dv]);
    }
}

// ---------------------------------------------------------------------------
// Tensor-core causal flash attention (tf32 mma.sync) -- unchanged
// ---------------------------------------------------------------------------
constexpr int FK0 = 0;
constexpr int FV0 = 12544;
constexpr int FK1 = 21248;
constexpr int FV1 = 33792;
constexpr int FPS = 42496;
constexpr int FRM = 46848;
constexpr int FRS = 46976;
constexpr unsigned FL_SMEM_BYTES = 47104u * 4u;

__global__ __launch_bounds__(256, 1)
void flash_mma(const float* __restrict__ Qf, const float* __restrict__ Kf,
               const float* __restrict__ Vf, float* __restrict__ Out) {
    extern __shared__ float sm[];
    const uint32_t sb = smem_u32(sm);

    const int t    = threadIdx.x;
    const int wid  = t >> 5;
    const int lane = t & 31;
    const int g    = lane >> 2;
    const int tig  = lane & 3;
    const int wr   = wid >> 1;
    const int wc   = wid & 1;
    const int bh   = blockIdx.x;
    const int qt   = (int)gridDim.y - 1 - (int)blockIdx.y;
    const int q0   = qt * 64;
    const int b    = bh >> 4, h = bh & 15;

    const float* Kbase = Kf + (size_t)bh * S_ * QD_;
    const float* Vbase = Vf + (size_t)bh * S_ * VD_;

#define KV_LOAD(bufK, bufV, jj)                                                 \
    do {                                                                        \
        const float* Kb_ = Kbase + (size_t)(jj) * 64 * QD_;                     \
        const float* Vb_ = Vbase + (size_t)(jj) * 64 * VD_;                     \
        _Pragma("unroll")                                                       \
        for (int i_ = 0; i_ < 12; i_++) {                                       \
            const int f_ = t + i_ * 256;                                        \
            const int r_ = f_ / 48, c_ = (f_ % 48) * 4;                         \
            CPA16(sb + (uint32_t)((bufK) + r_ * 196 + c_) * 4u,                 \
                  Kb_ + r_ * QD_ + c_, 16);                                     \
        }                                                                       \
        _Pragma("unroll")                                                       \
        for (int i_ = 0; i_ < 8; i_++) {                                        \
            const int f_ = t + i_ * 256;                                        \
            const int r_ = f_ >> 5, c_ = (f_ & 31) * 4;                         \
            CPA16(sb + (uint32_t)((bufV) + r_ * 136 + c_) * 4u,                 \
                  Vb_ + r_ * VD_ + c_, 16);                                     \
        }                                                                       \
        asm volatile("cp.async.commit_group;" ::: "memory");                    \
    } while (0)

    {
        const float* Qb = Qf + ((size_t)bh * S_ + q0) * QD_;
#pragma unroll
        for (int i = 0; i < 12; i++) {
            const int f = t + i * 256;
            const int r = f / 48, c = (f % 48) * 4;
            CPA16(sb + (uint32_t)(FK1 + r * 196 + c) * 4u, Qb + r * QD_ + c, 16);
        }
        asm volatile("cp.async.commit_group;" ::: "memory");
    }
    KV_LOAD(FK0, FV0, 0);
    asm volatile("cp.async.wait_group 1;" ::: "memory");
    __syncthreads();

    uint32_t qr[24][4];
    {
        const float* Qs = sm + FK1 + (wr * 16 + g) * 196 + tig;
#pragma unroll
        for (int ks = 0; ks < 24; ks++) {
            qr[ks][0] = __float_as_uint(Qs[ks * 8]);
            qr[ks][1] = __float_as_uint(Qs[ks * 8 + 8 * 196]);
            qr[ks][2] = __float_as_uint(Qs[ks * 8 + 4]);
            qr[ks][3] = __float_as_uint(Qs[ks * 8 + 8 * 196 + 4]);
        }
    }
    __syncthreads();
    if (qt >= 1) KV_LOAD(FK1, FV1, 1);

    float mi0 = -INFINITY, mi1 = -INFINITY, li0 = 0.f, li1 = 0.f;
    float acc[8][4];
#pragma unroll
    for (int nt = 0; nt < 8; nt++)
#pragma unroll
        for (int c = 0; c < 4; c++) acc[nt][c] = 0.f;

    const int row0 = wr * 16 + g;
    const int row1 = row0 + 8;

    for (int j = 0; j <= qt; ++j) {
        if (j < qt) asm volatile("cp.async.wait_group 1;" ::: "memory");
        else        asm volatile("cp.async.wait_group 0;" ::: "memory");
        __syncthreads();

        const int KB = (j & 1) ? FK1 : FK0;
        const int VB = (j & 1) ? FV1 : FV0;

        float s4[4][4];
#pragma unroll
        for (int nt = 0; nt < 4; nt++)
#pragma unroll
            for (int c = 0; c < 4; c++) s4[nt][c] = 0.f;

#pragma unroll
        for (int ks = 0; ks < 24; ks++) {
            uint32_t bf[4][2];
#pragma unroll
            for (int nt = 0; nt < 4; nt++) {
                const float* kp = sm + KB + (wc * 32 + nt * 8 + g) * 196 + ks * 8 + tig;
                bf[nt][0] = __float_as_uint(kp[0]);
                bf[nt][1] = __float_as_uint(kp[4]);
            }
#pragma unroll
            for (int nt = 0; nt < 4; nt++)
                MMA_TF32(s4[nt], qr[ks], bf[nt]);
        }

        if (j == qt) {
#pragma unroll
            for (int nt = 0; nt < 4; nt++) {
                const int col = wc * 32 + nt * 8 + tig * 2;
                if (col     > row0) s4[nt][0] = -1e30f;
                if (col + 1 > row0) s4[nt][1] = -1e30f;
                if (col     > row1) s4[nt][2] = -1e30f;
                if (col + 1 > row1) s4[nt][3] = -1e30f;
            }
        }

        float pm0 = fmaxf(fmaxf(s4[0][0], s4[0][1]), fmaxf(s4[1][0], s4[1][1]));
        pm0 = fmaxf(pm0, fmaxf(fmaxf(s4[2][0], s4[2][1]), fmaxf(s4[3][0], s4[3][1])));
        float pm1 = fmaxf(fmaxf(s4[0][2], s4[0][3]), fmaxf(s4[1][2], s4[1][3]));
        pm1 = fmaxf(pm1, fmaxf(fmaxf(s4[2][2], s4[2][3]), fmaxf(s4[3][2], s4[3][3])));
        pm0 = fmaxf(pm0, __shfl_xor_sync(0xffffffffu, pm0, 1));
        pm0 = fmaxf(pm0, __shfl_xor_sync(0xffffffffu, pm0, 2));
        pm1 = fmaxf(pm1, __shfl_xor_sync(0xffffffffu, pm1, 1));
        pm1 = fmaxf(pm1, __shfl_xor_sync(0xffffffffu, pm1, 2));
        if (tig == 0) {
            sm[FRM + wc * 64 + row0] = pm0;
            sm[FRM + wc * 64 + row1] = pm1;
        }
        __syncthreads();
        const float rm0 = fmaxf(sm[FRM + row0], sm[FRM + 64 + row0]);
        const float rm1 = fmaxf(sm[FRM + row1], sm[FRM + 64 + row1]);
        const float mn0 = fmaxf(mi0, rm0), mn1 = fmaxf(mi1, rm1);
        const float corr0 = __expf(mi0 - mn0), corr1 = __expf(mi1 - mn1);
        mi0 = mn0; mi1 = mn1;

        float rs0 = 0.f, rs1 = 0.f;
#pragma unroll
        for (int nt = 0; nt < 4; nt++) {
            s4[nt][0] = __expf(s4[nt][0] - mn0); rs0 += s4[nt][0];
            s4[nt][1] = __expf(s4[nt][1] - mn0); rs0 += s4[nt][1];
            s4[nt][2] = __expf(s4[nt][2] - mn1); rs1 += s4[nt][2];
            s4[nt][3] = __expf(s4[nt][3] - mn1); rs1 += s4[nt][3];
        }
        rs0 += __shfl_xor_sync(0xffffffffu, rs0, 1);
        rs0 += __shfl_xor_sync(0xffffffffu, rs0, 2);
        rs1 += __shfl_xor_sync(0xffffffffu, rs1, 1);
        rs1 += __shfl_xor_sync(0xffffffffu, rs1, 2);
        if (tig == 0) {
            sm[FRS + wc * 64 + row0] = rs0;
            sm[FRS + wc * 64 + row1] = rs1;
        }
#pragma unroll
        for (int nt = 0; nt < 4; nt++) {
            const int col = wc * 32 + nt * 8 + tig * 2;
            *(float2*)&sm[FPS + row0 * 68 + col] =
                make_float2(to_tf32(s4[nt][0]), to_tf32(s4[nt][1]));
            *(float2*)&sm[FPS + row1 * 68 + col] =
                make_float2(to_tf32(s4[nt][2]), to_tf32(s4[nt][3]));
        }
        __syncthreads();

        li0 = li0 * corr0 + sm[FRS + row0] + sm[FRS + 64 + row0];
        li1 = li1 * corr1 + sm[FRS + row1] + sm[FRS + 64 + row1];
#pragma unroll
        for (int nt = 0; nt < 8; nt++) {
            acc[nt][0] *= corr0; acc[nt][1] *= corr0;
            acc[nt][2] *= corr1; acc[nt][3] *= corr1;
        }

#pragma unroll
        for (int ks = 0; ks < 8; ks++) {
            uint32_t a[4];
            const float* pp = sm + FPS + row0 * 68 + ks * 8 + tig;
            a[0] = __float_as_uint(pp[0]);
            a[1] = __float_as_uint(pp[8 * 68]);
            a[2] = __float_as_uint(pp[4]);
            a[3] = __float_as_uint(pp[8 * 68 + 4]);
#pragma unroll
            for (int nt = 0; nt < 8; nt++) {
                uint32_t bf[2];
                const float* vp = sm + VB + (ks * 8 + tig) * 136 + wc * 64 + nt * 8 + g;
                bf[0] = __float_as_uint(vp[0]);
                bf[1] = __float_as_uint(vp[4 * 136]);
                MMA_TF32(acc[nt], a, bf);
            }
        }
        __syncthreads();

        if (j + 2 <= qt) {
            if (j & 1) KV_LOAD(FK1, FV1, j + 2);
            else       KV_LOAD(FK0, FV0, j + 2);
        }
    }
#undef KV_LOAD

    const float linv0 = 1.0f / li0;
    const float linv1 = 1.0f / li1;
    const size_t r0g = (size_t)(b * S_ + q0 + row0) * (H_ * VD_) + h * VD_;
    const size_t r1g = (size_t)(b * S_ + q0 + row1) * (H_ * VD_) + h * VD_;
#pragma unroll
    for (int nt = 0; nt < 8; nt++) {
        const int col = wc * 64 + nt * 8 + tig * 2;
        *(float2*)&Out[r0g + col] =
            make_float2(to_tf32(acc[nt][0] * linv0), to_tf32(acc[nt][1] * linv0));
        *(float2*)&Out[r1g + col] =
            make_float2(to_tf32(acc[nt][2] * linv1), to_tf32(acc[nt][3] * linv1));
    }
}

// ---------------------------------------------------------------------------
// Launch
// ---------------------------------------------------------------------------
extern "C" void kernel_launch(void* const* d_in, const int* in_sizes, int n_in,
                              void* d_out, int out_size) {
    const float* x      = (const float*)d_in[0];
    const float* rope   = (const float*)d_in[1];
    const float* wq     = (const float*)d_in[2];
    const float* wkva   = (const float*)d_in[3];
    const float* norm_w = (const float*)d_in[4];
    const float* wkvb   = (const float*)d_in[5];
    const float* wo     = (const float*)d_in[6];
    float* out = (float*)d_out;

    float *p_qckv, *p_norm, *p_kv, *p_qf, *p_kf, *p_v, *p_attn;
    float *p_xr, *p_wqkva, *p_wkvbr, *p_wor;
    cudaGetSymbolAddress((void**)&p_qckv,  g_qckv);
    cudaGetSymbolAddress((void**)&p_norm,  g_norm);
    cudaGetSymbolAddress((void**)&p_kv,    g_kv);
    cudaGetSymbolAddress((void**)&p_qf,    g_qf);
    cudaGetSymbolAddress((void**)&p_kf,    g_kf);
    cudaGetSymbolAddress((void**)&p_v,     g_v);
    cudaGetSymbolAddress((void**)&p_attn,  g_attn);
    cudaGetSymbolAddress((void**)&p_xr,    g_xr);
    cudaGetSymbolAddress((void**)&p_wqkva, g_wqkva);
    cudaGetSymbolAddress((void**)&p_wkvbr, g_wkvbr);
    cudaGetSymbolAddress((void**)&p_wor,   g_wor);

    cudaFuncSetAttribute(mma_gemm, cudaFuncAttributeMaxDynamicSharedMemorySize,
                         MG_SMEM_BYTES);
    cudaFuncSetAttribute(flash_mma, cudaFuncAttributeMaxDynamicSharedMemorySize,
                         FL_SMEM_BYTES);

    // 0) round operands to tf32 (wq & wkva concatenated into fused B)
    {
        int n;
        n = BS_ * DIM_ / 4;
        round_tf32_kernel<<<1024, 256>>>((const float4*)x, (float4*)p_xr, n);
        n = H_ * QD_ * DIM_ / 4;
        round_tf32_kernel<<<1024, 256>>>((const float4*)wq, (float4*)p_wqkva, n);
        n = (KV_LORA_ + ROPE_) * DIM_ / 4;
        round_tf32_kernel<<<512, 256>>>((const float4*)wkva,
                                        (float4*)(p_wqkva + (size_t)H_ * QD_ * DIM_), n);
        n = H_ * 256 * KV_LORA_ / 4;
        round_tf32_kernel<<<512, 256>>>((const float4*)wkvb, (float4*)p_wkvbr, n);
        n = DIM_ * H_ * VD_ / 4;
        round_tf32_kernel<<<1024, 256>>>((const float4*)wo, (float4*)p_wor, n);
    }

    // 1) qckv = x @ [wq; wkva]^T   [4096, 3648]
    mma_gemm<<<dim3(15, 32), 256, MG_SMEM_BYTES>>>(p_xr, p_wqkva, p_qckv, NQC_, DIM_);
    // 2) RMSNorm
    rmsnorm_kernel<<<BS_, 128>>>(p_qckv, norm_w, p_norm);
    // 3) kv = norm @ wkvb^T        [4096, 4096]
    mma_gemm<<<dim3(16, 32), 256, MG_SMEM_BYTES>>>(p_norm, p_wkvbr, p_kv, H_ * 256, KV_LORA_);
    // 4) RoPE + assemble
    assemble_kernel<<<BS_, 256>>>(p_qckv, p_kv, rope, p_qf, p_kf, p_v);
    // 5) tensor-core causal flash attention
    flash_mma<<<dim3(B_ * H_, S_ / 64), 256, FL_SMEM_BYTES>>>(p_qf, p_kf, p_v, p_attn);
    // 6) out = attn @ wo^T         [4096, 2048]
    mma_gemm<<<dim3(8, 32), 256, MG_SMEM_BYTES>>>(p_attn, p_wor, out, DIM_, DIM_);
}